// round 1
// baseline (speedup 1.0000x reference)
#include <cuda_runtime.h>
#include <math.h>

#define BATCH 8
#define HWD 128
#define C1 128
#define DM 256
#define LSEQ 1024
#define NROWS (BATCH*LSEQ)
#define DSTATE 16
#define HEADDIM 64
#define DINNER 512
#define NHEADS 8
#define CONVDIM 544
#define DINPROJ 1064
#define NCHUNK 16
#define QCH 64
#define EPSV 1e-5f

// ---------------- scratch (device globals; no runtime allocation) ----------------
__device__ float g_h1[(size_t)BATCH*C1*HWD*HWD];        // stem1 output (post gelu)
__device__ float g_im2col[(size_t)NROWS*2048];          // conv2 patches
__device__ float g_w2t[2048*DM];                        // transposed stem_w2
__device__ float g_tok[NROWS*DM];                       // token stream / residual
__device__ float g_zx[(size_t)NROWS*DINPROJ];           // in_proj output
__device__ float g_xbc[(size_t)NROWS*CONVDIM];          // conv1d+silu output
__device__ float g_dtv[NROWS*NHEADS];                   // softplus dt
__device__ float g_dA[NROWS*NHEADS];                    // per-step decay  [(b*8+h)*L + l]
__device__ float g_cdA[NROWS*NHEADS];                   // within-chunk cumulative decay
__device__ float g_ybuf[(size_t)NROWS*DINNER];          // scan output y
__device__ float g_gated[(size_t)NROWS*DINNER];         // gated+rmsnormed
__device__ float g_S[BATCH*NHEADS*NCHUNK*HEADDIM*DSTATE];   // chunk-local end states
__device__ float g_hs[BATCH*NHEADS*NCHUNK*HEADDIM*DSTATE];  // chunk-start states
__device__ float g_mproj[NROWS*DM];                     // out_proj output

__device__ __forceinline__ float geluf(float t){ return 0.5f*t*(1.0f+erff(t*0.70710678118654752f)); }
__device__ __forceinline__ float siluf(float t){ return t/(1.0f+expf(-t)); }

__device__ __forceinline__ float blockReduceSum(float v, float* sred){
  int lane = threadIdx.x & 31, wid = threadIdx.x >> 5;
  #pragma unroll
  for (int o=16;o>0;o>>=1) v += __shfl_xor_sync(0xffffffffu,v,o);
  if (lane==0) sred[wid]=v;
  __syncthreads();
  int nw = (blockDim.x+31)>>5;
  if (threadIdx.x < 32){
    float r = (threadIdx.x < nw) ? sred[threadIdx.x] : 0.f;
    #pragma unroll
    for (int o=16;o>0;o>>=1) r += __shfl_xor_sync(0xffffffffu,r,o);
    if (threadIdx.x==0) sred[0]=r;
  }
  __syncthreads();
  float r = sred[0];
  __syncthreads();
  return r;
}

// ---------------- stem conv1: 3x3 SAME, 3->128, BN+GELU ----------------
__global__ __launch_bounds__(128) void conv1_kernel(const float* __restrict__ x,
    const float* __restrict__ w, const float* __restrict__ g1, const float* __restrict__ b1)
{
  __shared__ float sw[C1*27];
  __shared__ float sg[C1], sb[C1];
  int xx = threadIdx.x, y = blockIdx.x, b = blockIdx.y;
  for (int i=xx;i<C1*27;i+=128) sw[i]=w[i];
  sg[xx]=g1[xx]; sb[xx]=b1[xx];
  __syncthreads();
  float in[27];
  int q=0;
  #pragma unroll
  for (int ci=0;ci<3;ci++)
    #pragma unroll
    for (int ky=0;ky<3;ky++){
      int iy=y+ky-1;
      #pragma unroll
      for (int kx=0;kx<3;kx++){
        int ix=xx+kx-1;
        in[q++] = (iy>=0 && iy<HWD && ix>=0 && ix<HWD) ? x[((b*3+ci)*HWD+iy)*HWD+ix] : 0.f;
      }
    }
  for (int co=0;co<C1;co++){
    float acc=0.f;
    #pragma unroll
    for (int t=0;t<27;t++) acc += in[t]*sw[co*27+t];
    float v = acc*sg[co]+sb[co];
    g_h1[(((size_t)b*C1+co)*HWD+y)*HWD+xx] = geluf(v);
  }
}

// ---------------- transpose stem_w2 (256,2048) -> (2048,256) ----------------
__global__ void w2t_kernel(const float* __restrict__ w2){
  int idx = blockIdx.x*256 + threadIdx.x;
  int co = idx & 255, k = idx >> 8;
  g_w2t[idx] = w2[co*2048 + k];
}

// ---------------- im2col for conv2 (4x4 stride 4 = non-overlapping) ----------------
__global__ void im2col_kernel(){
  size_t idx = (size_t)blockIdx.x*256 + threadIdx.x;   // NROWS*2048
  int k = (int)(idx & 2047); size_t row = idx >> 11;
  int b = (int)(row >> 10); int s = (int)(row & 1023); int y = s >> 5; int xq = s & 31;
  int ci = k >> 4, ky = (k>>2)&3, kx = k&3;
  g_im2col[idx] = g_h1[(((size_t)b*C1+ci)*HWD + y*4+ky)*HWD + xq*4+kx];
}

// ---------------- generic fp32 tiled GEMM: C[M,N]=A[M,K]@B[K,N]; M%128==0, K%8==0 ----------------
__global__ __launch_bounds__(256) void gemm_kernel(
    const float* __restrict__ A, const float* __restrict__ Bm, float* __restrict__ C,
    int M, int N, int K, const float* __restrict__ eg, const float* __restrict__ eb, int epi)
{
  __shared__ float As[8][128];
  __shared__ float Bs[8][128];
  int tid = threadIdx.x;
  int row0 = blockIdx.y*128, col0 = blockIdx.x*128;
  int tx = tid & 15, ty = tid >> 4;
  float acc[8][8];
  #pragma unroll
  for (int i=0;i<8;i++)
    #pragma unroll
    for (int j=0;j<8;j++) acc[i][j]=0.f;
  int a_r = tid >> 1, a_k = (tid & 1) * 4;
  int b_r = tid >> 5, b_c = (tid & 31) * 4;
  for (int k0=0;k0<K;k0+=8){
    float4 av = *(const float4*)(A + (size_t)(row0+a_r)*K + k0 + a_k);
    As[a_k+0][a_r]=av.x; As[a_k+1][a_r]=av.y; As[a_k+2][a_r]=av.z; As[a_k+3][a_r]=av.w;
    int bc = col0 + b_c;
    float4 bv = make_float4(0.f,0.f,0.f,0.f);
    const float* bp = Bm + (size_t)(k0+b_r)*N;
    if (bc + 3 < N) bv = *(const float4*)(bp + bc);
    else {
      if (bc+0 < N) bv.x = bp[bc+0];
      if (bc+1 < N) bv.y = bp[bc+1];
      if (bc+2 < N) bv.z = bp[bc+2];
      if (bc+3 < N) bv.w = bp[bc+3];
    }
    *(float4*)&Bs[b_r][b_c] = bv;
    __syncthreads();
    #pragma unroll
    for (int kk=0;kk<8;kk++){
      float4 a0 = *(const float4*)&As[kk][ty*4];
      float4 a1 = *(const float4*)&As[kk][64+ty*4];
      float4 b0 = *(const float4*)&Bs[kk][tx*4];
      float4 b1 = *(const float4*)&Bs[kk][64+tx*4];
      float ra[8]={a0.x,a0.y,a0.z,a0.w,a1.x,a1.y,a1.z,a1.w};
      float rb[8]={b0.x,b0.y,b0.z,b0.w,b1.x,b1.y,b1.z,b1.w};
      #pragma unroll
      for (int i=0;i<8;i++)
        #pragma unroll
        for (int j=0;j<8;j++) acc[i][j] += ra[i]*rb[j];
    }
    __syncthreads();
  }
  #pragma unroll
  for (int i=0;i<8;i++){
    int r = row0 + ((i<4)? ty*4+i : 64+ty*4+(i-4));
    #pragma unroll
    for (int j=0;j<8;j++){
      int c = col0 + ((j<4)? tx*4+j : 64+tx*4+(j-4));
      if (c < N){
        float v = acc[i][j];
        if (epi==1){ v = v*eg[c]+eb[c]; v = geluf(v); }
        C[(size_t)r*N + c] = v;
      }
    }
  }
}

// ---------------- depthwise causal conv1d (width 4) + silu ----------------
__global__ void dwconv_kernel(const float* __restrict__ cw, const float* __restrict__ cb, int layer){
  int idx = blockIdx.x*256 + threadIdx.x;
  int c = idx % CONVDIM; int row = idx / CONVDIM;
  int l = row & 1023, b = row >> 10;
  const float* wp = cw + (layer*CONVDIM + c)*4;
  float acc = cb[layer*CONVDIM + c];
  #pragma unroll
  for (int k=0;k<4;k++){
    int ls = l + k - 3;
    if (ls >= 0) acc += g_zx[((size_t)(b<<10)+ls)*DINPROJ + DINNER + c] * wp[k];
  }
  g_xbc[(size_t)row*CONVDIM + c] = siluf(acc);
}

// ---------------- dt = softplus(raw + bias), dA = exp(-exp(A_log)*dt) ----------------
__global__ void dtda_kernel(const float* __restrict__ dt_bias, const float* __restrict__ A_log, int layer){
  int idx = blockIdx.x*256+threadIdx.x;            // NROWS*NHEADS = 65536
  int h = idx & 7; int row = idx >> 3;
  float raw = g_zx[(size_t)row*DINPROJ + 1056 + h] + dt_bias[layer*8+h];
  float dt = (raw > 20.f) ? raw : log1pf(expf(raw));
  float dA = expf(-expf(A_log[layer*8+h])*dt);
  g_dtv[row*8+h] = dt;
  int l = row & 1023, b = row >> 10;
  g_dA[(size_t)(b*8+h)*LSEQ + l] = dA;
}

// ---------------- scan pass 1: chunk-local sequential scan from h=0 ----------------
__global__ __launch_bounds__(64) void scan1_kernel(){
  __shared__ float sxdt[QCH][HEADDIM];
  __shared__ float sB[QCH][DSTATE];
  __shared__ float sC[QCH][DSTATE];
  __shared__ float sdA[QCH];
  int tid = threadIdx.x;                     // = p
  int c = blockIdx.x & 15, h = (blockIdx.x>>4)&7, b = blockIdx.x>>7;
  for (int s=0;s<QCH;s++){
    int l = c*QCH+s; size_t row = (size_t)b*LSEQ + l;
    float dtv = g_dtv[row*NHEADS + h];
    sxdt[s][tid] = g_xbc[row*CONVDIM + h*HEADDIM + tid] * dtv;
    if (tid < DSTATE) sB[s][tid] = g_xbc[row*CONVDIM + DINNER + tid];
    else if (tid < 2*DSTATE) sC[s][tid-DSTATE] = g_xbc[row*CONVDIM + DINNER + DSTATE + (tid-DSTATE)];
    else if (tid == 32) sdA[s] = g_dA[(size_t)(b*NHEADS+h)*LSEQ + l];
  }
  __syncthreads();
  if (tid == 0){
    float r = 1.f;
    for (int s=0;s<QCH;s++){ r *= sdA[s]; g_cdA[(size_t)(b*NHEADS+h)*LSEQ + c*QCH + s] = r; }
  }
  float hr[DSTATE];
  #pragma unroll
  for (int n=0;n<DSTATE;n++) hr[n]=0.f;
  for (int s=0;s<QCH;s++){
    float dAv = sdA[s];
    float xv = sxdt[s][tid];
    float Bv[DSTATE], Cv[DSTATE];
    *(float4*)&Bv[0]  = *(const float4*)&sB[s][0];
    *(float4*)&Bv[4]  = *(const float4*)&sB[s][4];
    *(float4*)&Bv[8]  = *(const float4*)&sB[s][8];
    *(float4*)&Bv[12] = *(const float4*)&sB[s][12];
    *(float4*)&Cv[0]  = *(const float4*)&sC[s][0];
    *(float4*)&Cv[4]  = *(const float4*)&sC[s][4];
    *(float4*)&Cv[8]  = *(const float4*)&sC[s][8];
    *(float4*)&Cv[12] = *(const float4*)&sC[s][12];
    float y = 0.f;
    #pragma unroll
    for (int n=0;n<DSTATE;n++){
      hr[n] = hr[n]*dAv + xv*Bv[n];
      y += hr[n]*Cv[n];
    }
    size_t row = (size_t)b*LSEQ + c*QCH + s;
    g_ybuf[row*DINNER + h*HEADDIM + tid] = y;
  }
  size_t base = ((size_t)(b*NHEADS+h)*NCHUNK + c)*1024 + tid*DSTATE;
  #pragma unroll
  for (int n=0;n<DSTATE;n++) g_S[base+n] = hr[n];
}

// ---------------- scan pass 2: combine chunk states across 16 chunks ----------------
__global__ __launch_bounds__(1024) void scan2_kernel(){
  int bh = blockIdx.x; int tid = threadIdx.x;
  float hprev = 0.f;
  for (int c=0;c<NCHUNK;c++){
    size_t base = ((size_t)bh*NCHUNK + c)*1024;
    g_hs[base + tid] = hprev;
    float Ac = g_cdA[(size_t)bh*LSEQ + c*QCH + QCH-1];
    hprev = hprev*Ac + g_S[base + tid];
  }
}

// ---------------- scan pass 3: y += cdA[t]*(C_t . h_start) + xs*D_skip ----------------
__global__ __launch_bounds__(256) void scan3_kernel(const float* __restrict__ Dskip, int layer){
  __shared__ float sCc[QCH*DSTATE];
  __shared__ float scd[QCH];
  int tid = threadIdx.x;
  int c = blockIdx.x & 15, h = (blockIdx.x>>4)&7, b = blockIdx.x>>7;
  for (int k=tid;k<QCH*DSTATE;k+=256){
    int s = k>>4, n = k&15;
    sCc[k] = g_xbc[((size_t)b*LSEQ + c*QCH + s)*CONVDIM + DINNER + DSTATE + n];
  }
  if (tid < QCH) scd[tid] = g_cdA[(size_t)(b*NHEADS+h)*LSEQ + c*QCH + tid];
  __syncthreads();
  int tg = tid >> 6, p = tid & 63;
  float hreg[DSTATE];
  size_t hbase = ((size_t)(b*NHEADS+h)*NCHUNK + c)*1024 + p*DSTATE;
  #pragma unroll
  for (int n=0;n<DSTATE;n++) hreg[n] = g_hs[hbase+n];
  float Dh = Dskip[layer*NHEADS+h];
  for (int t=tg*16; t<tg*16+16; t++){
    size_t row = (size_t)b*LSEQ + c*QCH + t;
    float acc = 0.f;
    #pragma unroll
    for (int n=0;n<DSTATE;n++) acc += sCc[t*DSTATE+n]*hreg[n];
    float xs = g_xbc[row*CONVDIM + h*HEADDIM + p];
    size_t yi = row*DINNER + h*HEADDIM + p;
    g_ybuf[yi] += scd[t]*acc + xs*Dh;
  }
}

// ---------------- gate with silu(z), RMS-norm over 512, * rms_w ----------------
__global__ __launch_bounds__(128) void gate_kernel(const float* __restrict__ rms_w, int layer){
  __shared__ float sred[32];
  size_t row = blockIdx.x;
  int tid = threadIdx.x;
  float v[4]; float ss = 0.f;
  #pragma unroll
  for (int j=0;j<4;j++){
    int d = tid + j*128;
    float z = g_zx[row*DINPROJ + d];
    float yv = g_ybuf[row*DINNER + d];
    float g = yv * siluf(z);
    v[j]=g; ss += g*g;
  }
  ss = blockReduceSum(ss, sred);
  float rstd = rsqrtf(ss*(1.0f/DINNER) + EPSV);
  #pragma unroll
  for (int j=0;j<4;j++){
    int d = tid + j*128;
    g_gated[row*DINNER + d] = v[j]*rstd*rms_w[layer*DINNER + d];
  }
}

// ---------------- residual + LayerNorm over 256 -> g_tok ----------------
__global__ __launch_bounds__(256) void lnres_kernel(const float* __restrict__ lg, const float* __restrict__ lb, int layer){
  __shared__ float sred[32];
  size_t row = blockIdx.x; int d = threadIdx.x;
  float v = g_mproj[row*DM + d] + g_tok[row*DM + d];
  float mean = blockReduceSum(v, sred) * (1.0f/DM);
  float dv = v - mean;
  float var = blockReduceSum(dv*dv, sred) * (1.0f/DM);
  g_tok[row*DM + d] = dv*rsqrtf(var+EPSV)*lg[layer*DM+d] + lb[layer*DM+d];
}

// ---------------- mean-pool + LN + head ----------------
__global__ __launch_bounds__(256) void head_kernel(const float* __restrict__ hg, const float* __restrict__ hb,
    const float* __restrict__ hw, const float* __restrict__ hbias, float* __restrict__ out){
  __shared__ float sred[32];
  __shared__ float sn[DM];
  int b = blockIdx.x, d = threadIdx.x;
  float s=0.f;
  for (int l=0;l<LSEQ;l++) s += g_tok[((size_t)b*LSEQ+l)*DM + d];
  float pooled = s*(1.0f/LSEQ);
  float mean = blockReduceSum(pooled, sred)*(1.0f/DM);
  float dv = pooled-mean;
  float var = blockReduceSum(dv*dv, sred)*(1.0f/DM);
  sn[d] = dv*rsqrtf(var+EPSV)*hg[d]+hb[d];
  __syncthreads();
  if (d < 10){
    float acc = hbias[d];
    for (int k=0;k<DM;k++) acc += sn[k]*hw[k*10+d];
    out[b*10+d] = acc;
  }
}

// ---------------- host launcher ----------------
extern "C" void kernel_launch(void* const* d_in, const int* in_sizes, int n_in,
                              void* d_out, int out_size)
{
  const float* x       = (const float*)d_in[0];
  const float* w1      = (const float*)d_in[1];
  const float* sg1     = (const float*)d_in[2];
  const float* sb1     = (const float*)d_in[3];
  const float* w2      = (const float*)d_in[4];
  const float* sg2     = (const float*)d_in[5];
  const float* sb2     = (const float*)d_in[6];
  const float* in_w    = (const float*)d_in[7];
  const float* conv_w  = (const float*)d_in[8];
  const float* conv_b  = (const float*)d_in[9];
  const float* dt_bias = (const float*)d_in[10];
  const float* A_log   = (const float*)d_in[11];
  const float* D_skip  = (const float*)d_in[12];
  const float* rms_w   = (const float*)d_in[13];
  const float* out_w   = (const float*)d_in[14];
  const float* ln_g    = (const float*)d_in[15];
  const float* ln_b    = (const float*)d_in[16];
  const float* hg      = (const float*)d_in[17];
  const float* hb      = (const float*)d_in[18];
  const float* hw      = (const float*)d_in[19];
  const float* hbias   = (const float*)d_in[20];
  float* out = (float*)d_out;

  void *pa, *pb, *pc, *pd, *pe, *pf;
  cudaGetSymbolAddress(&pa, g_im2col);
  cudaGetSymbolAddress(&pb, g_w2t);
  cudaGetSymbolAddress(&pc, g_tok);
  cudaGetSymbolAddress(&pd, g_zx);
  cudaGetSymbolAddress(&pe, g_gated);
  cudaGetSymbolAddress(&pf, g_mproj);
  float* p_im2col = (float*)pa;
  float* p_w2t    = (float*)pb;
  float* p_tok    = (float*)pc;
  float* p_zx     = (float*)pd;
  float* p_gated  = (float*)pe;
  float* p_m      = (float*)pf;

  conv1_kernel<<<dim3(HWD,BATCH),128>>>(x, w1, sg1, sb1);
  w2t_kernel<<<2048,256>>>(w2);
  im2col_kernel<<<65536,256>>>();
  gemm_kernel<<<dim3(2,64),256>>>(p_im2col, p_w2t, p_tok, NROWS, DM, 2048, sg2, sb2, 1);

  for (int i=0;i<4;i++){
    gemm_kernel<<<dim3(9,64),256>>>(p_tok, in_w + (size_t)i*DM*DINPROJ, p_zx,
                                    NROWS, DINPROJ, DM, (const float*)0, (const float*)0, 0);
    dwconv_kernel<<<(NROWS*CONVDIM)/256,256>>>(conv_w, conv_b, i);
    dtda_kernel<<<(NROWS*NHEADS)/256,256>>>(dt_bias, A_log, i);
    scan1_kernel<<<1024,64>>>();
    scan2_kernel<<<64,1024>>>();
    scan3_kernel<<<1024,256>>>(D_skip, i);
    gate_kernel<<<NROWS,128>>>(rms_w, i);
    gemm_kernel<<<dim3(2,64),256>>>(p_gated, out_w + (size_t)i*DINNER*DM, p_m,
                                    NROWS, DM, DINNER, (const float*)0, (const float*)0, 0);
    lnres_kernel<<<NROWS,256>>>(ln_g, ln_b, i);
  }

  head_kernel<<<BATCH,256>>>(hg, hb, hw, hbias, out);
}

// round 3
// speedup vs baseline: 1.1014x; 1.1014x over previous
#include <cuda_runtime.h>
#include <cuda_bf16.h>
#include <math.h>
#include <stdint.h>

#define BATCH 8
#define HWD 128
#define C1 128
#define DM 256
#define LSEQ 1024
#define NROWS (BATCH*LSEQ)
#define DSTATE 16
#define HEADDIM 64
#define DINNER 512
#define NHEADS 8
#define CONVDIM 544
#define DINPROJ 1064
#define NPAD_IN 1152
#define NCHUNK 16
#define QCH 64
#define EPSV 1e-5f

typedef __nv_bfloat16 bf16;

// ---------------- scratch (device globals) ----------------
__device__ float g_h1[(size_t)BATCH*C1*HWD*HWD];
__device__ bf16  g_imh[(size_t)NROWS*2048];
__device__ bf16  g_iml[(size_t)NROWS*2048];
__device__ bf16  g_w2h[256*2048], g_w2l[256*2048];
__device__ float g_tok[NROWS*DM];
__device__ bf16  g_th[NROWS*DM], g_tl[NROWS*DM];
__device__ bf16  g_inwh[4*NPAD_IN*DM], g_inwl[4*NPAD_IN*DM];
__device__ bf16  g_owh[4*DM*DINNER], g_owl[4*DM*DINNER];
__device__ float g_zx[(size_t)NROWS*DINPROJ];
__device__ float g_xbc[(size_t)NROWS*CONVDIM];
__device__ float g_dtv[NROWS*NHEADS];
__device__ float g_dA[NROWS*NHEADS];
__device__ float g_cdA[NROWS*NHEADS];
__device__ float g_ybuf[(size_t)NROWS*DINNER];
__device__ bf16  g_gah[(size_t)NROWS*DINNER], g_gal[(size_t)NROWS*DINNER];
__device__ float g_S[BATCH*NHEADS*NCHUNK*HEADDIM*DSTATE];
__device__ float g_hs[BATCH*NHEADS*NCHUNK*HEADDIM*DSTATE];
__device__ float g_mproj[NROWS*DM];

__device__ __forceinline__ float geluf(float t){ return 0.5f*t*(1.0f+erff(t*0.70710678118654752f)); }
__device__ __forceinline__ float siluf(float t){ return t/(1.0f+expf(-t)); }
__device__ __forceinline__ void split2(float v, bf16& h, bf16& l){
  h = __float2bfloat16(v);
  l = __float2bfloat16(v - __bfloat162float(h));
}

__device__ __forceinline__ float blockReduceSum(float v, float* sred){
  int lane = threadIdx.x & 31, wid = threadIdx.x >> 5;
  #pragma unroll
  for (int o=16;o>0;o>>=1) v += __shfl_xor_sync(0xffffffffu,v,o);
  if (lane==0) sred[wid]=v;
  __syncthreads();
  int nw = (blockDim.x+31)>>5;
  if (threadIdx.x < 32){
    float r = (threadIdx.x < nw) ? sred[threadIdx.x] : 0.f;
    #pragma unroll
    for (int o=16;o>0;o>>=1) r += __shfl_xor_sync(0xffffffffu,r,o);
    if (threadIdx.x==0) sred[0]=r;
  }
  __syncthreads();
  float r = sred[0];
  __syncthreads();
  return r;
}

// ---------------- mma helpers (sm_80+ baseline PTX; works on sm_103) ----------------
__device__ __forceinline__ uint32_t smem_u32(const void* p){
  uint32_t a;
  asm("{ .reg .u64 t; cvta.to.shared.u64 t, %1; cvt.u32.u64 %0, t; }" : "=r"(a) : "l"(p));
  return a;
}
__device__ __forceinline__ void ldsm4(uint32_t& a0,uint32_t& a1,uint32_t& a2,uint32_t& a3, uint32_t addr){
  asm volatile("ldmatrix.sync.aligned.m8n8.x4.shared.b16 {%0,%1,%2,%3}, [%4];"
    : "=r"(a0),"=r"(a1),"=r"(a2),"=r"(a3) : "r"(addr));
}
__device__ __forceinline__ void ldsm2(uint32_t& a0,uint32_t& a1, uint32_t addr){
  asm volatile("ldmatrix.sync.aligned.m8n8.x2.shared.b16 {%0,%1}, [%2];"
    : "=r"(a0),"=r"(a1) : "r"(addr));
}
__device__ __forceinline__ void mma16816(float* d, uint32_t a0,uint32_t a1,uint32_t a2,uint32_t a3,
                                         uint32_t b0,uint32_t b1){
  asm volatile("mma.sync.aligned.m16n8k16.row.col.f32.bf16.bf16.f32 "
    "{%0,%1,%2,%3}, {%4,%5,%6,%7}, {%8,%9}, {%0,%1,%2,%3};"
    : "+f"(d[0]),"+f"(d[1]),"+f"(d[2]),"+f"(d[3])
    : "r"(a0),"r"(a1),"r"(a2),"r"(a3),"r"(b0),"r"(b1));
}

// ---------------- HMMA GEMM: C[M,N] = A[M,K] @ B^T, 3-term bf16 split ----------------
// A: [M][K] hi/lo, B: [Npad][K] hi/lo. Block tile 128x128, K-chunk 64.
// 8 warps = 2(m) x 4(n); warp tile 64x32.
#define SPAD 72                      // smem row stride (bf16): 144B, conflict-free ldmatrix
#define SA_BYTES (128*SPAD*2)        // 18432
#define MMG_SMEM (4*SA_BYTES)        // 73728 (also >= 128*132*4 staging)
__global__ __launch_bounds__(256) void mmagemm_kernel(
    const bf16* __restrict__ Ah, const bf16* __restrict__ Al,
    const bf16* __restrict__ Bh, const bf16* __restrict__ Bl,
    float* __restrict__ C, int K, int Nreal, int ldc, int epi,
    const float* __restrict__ eg, const float* __restrict__ eb,
    bf16* __restrict__ Chi, bf16* __restrict__ Clo)
{
  extern __shared__ char smem[];
  bf16* sAh = (bf16*)smem;
  bf16* sAl = (bf16*)(smem + SA_BYTES);
  bf16* sBh = (bf16*)(smem + 2*SA_BYTES);
  bf16* sBl = (bf16*)(smem + 3*SA_BYTES);
  uint32_t uAh = smem_u32(sAh), uAl = smem_u32(sAl);
  uint32_t uBh = smem_u32(sBh), uBl = smem_u32(sBl);

  int tid = threadIdx.x, lane = tid & 31, wid = tid >> 5;
  int row0 = blockIdx.y<<7, col0 = blockIdx.x<<7;
  int warp_m = wid >> 2, warp_n = wid & 3;
  int m0w = warp_m*64, n0w = warp_n*32;

  // global load mapping: 2 threads per row, each covers 32 cols (4 x 8bf16)
  int lr = tid >> 1, lh = tid & 1;
  size_t a_off = (size_t)(row0+lr)*K + lh*32;
  size_t b_off = (size_t)(col0+lr)*K + lh*32;
  uint32_t s_off = (uint32_t)(lr*SPAD + lh*32);

  // ldmatrix per-thread base offsets (bytes)
  uint32_t a_ld = (uint32_t)((m0w + (lane&7) + ((lane>>3)&1)*8)*SPAD*2 + (lane>>4)*16);
  uint32_t b_ld = (uint32_t)((n0w + (lane&7))*SPAD*2 + ((lane>>3)&1)*16);

  float d[4][4][4];
  #pragma unroll
  for (int i=0;i<4;i++)
    #pragma unroll
    for (int j=0;j<4;j++)
      #pragma unroll
      for (int q=0;q<4;q++) d[i][j][q]=0.f;

  int NCH = K>>6;
  for (int c=0;c<NCH;c++){
    if (c) __syncthreads();
    const uint4* pAh = (const uint4*)(Ah + a_off + (size_t)c*64);
    const uint4* pAl = (const uint4*)(Al + a_off + (size_t)c*64);
    const uint4* pBh = (const uint4*)(Bh + b_off + (size_t)c*64);
    const uint4* pBl = (const uint4*)(Bl + b_off + (size_t)c*64);
    #pragma unroll
    for (int j=0;j<4;j++) *(uint4*)(sAh + s_off + j*8) = pAh[j];
    #pragma unroll
    for (int j=0;j<4;j++) *(uint4*)(sAl + s_off + j*8) = pAl[j];
    #pragma unroll
    for (int j=0;j<4;j++) *(uint4*)(sBh + s_off + j*8) = pBh[j];
    #pragma unroll
    for (int j=0;j<4;j++) *(uint4*)(sBl + s_off + j*8) = pBl[j];
    __syncthreads();
    #pragma unroll
    for (int kk=0;kk<4;kk++){
      uint32_t bh[4][2], bl[4][2];
      #pragma unroll
      for (int j=0;j<4;j++){
        uint32_t ba = b_ld + (uint32_t)(j*8*SPAD*2 + kk*32);
        ldsm2(bh[j][0], bh[j][1], uBh + ba);
        ldsm2(bl[j][0], bl[j][1], uBl + ba);
      }
      #pragma unroll
      for (int i=0;i<4;i++){
        uint32_t ah0,ah1,ah2,ah3, al0,al1,al2,al3;
        uint32_t aa = a_ld + (uint32_t)(i*16*SPAD*2 + kk*32);
        ldsm4(ah0,ah1,ah2,ah3, uAh + aa);
        ldsm4(al0,al1,al2,al3, uAl + aa);
        #pragma unroll
        for (int j=0;j<4;j++){
          mma16816(d[i][j], ah0,ah1,ah2,ah3, bh[j][0],bh[j][1]);
          mma16816(d[i][j], ah0,ah1,ah2,ah3, bl[j][0],bl[j][1]);
          mma16816(d[i][j], al0,al1,al2,al3, bh[j][0],bh[j][1]);
        }
      }
    }
  }
  __syncthreads();

  // stage accums to smem (reuse), then vectorized epilogue
  float* stg = (float*)smem;            // [128][132]
  #pragma unroll
  for (int i=0;i<4;i++){
    int r0 = m0w + i*16 + (lane>>2);
    #pragma unroll
    for (int j=0;j<4;j++){
      int c0 = n0w + j*8 + (lane&3)*2;
      *(float2*)&stg[r0*132 + c0]     = make_float2(d[i][j][0], d[i][j][1]);
      *(float2*)&stg[(r0+8)*132 + c0] = make_float2(d[i][j][2], d[i][j][3]);
    }
  }
  __syncthreads();

  #pragma unroll 1
  for (int q=0;q<16;q++){
    int e = q*256 + tid;
    int rr = e>>5, cc = (e&31)*4;
    float vx = stg[rr*132+cc+0], vy = stg[rr*132+cc+1];
    float vz = stg[rr*132+cc+2], vw = stg[rr*132+cc+3];
    int gcol = col0 + cc, grow = row0 + rr;
    if (epi==1){
      vx = geluf(vx*eg[gcol+0]+eb[gcol+0]);
      vy = geluf(vy*eg[gcol+1]+eb[gcol+1]);
      vz = geluf(vz*eg[gcol+2]+eb[gcol+2]);
      vw = geluf(vw*eg[gcol+3]+eb[gcol+3]);
      *(float4*)(C + (size_t)grow*ldc + gcol) = make_float4(vx,vy,vz,vw);
      bf16 hx,lx,hy,ly,hz,lz,hw2,lw2;
      split2(vx,hx,lx); split2(vy,hy,ly); split2(vz,hz,lz); split2(vw,hw2,lw2);
      __nv_bfloat162* ph = (__nv_bfloat162*)(Chi + (size_t)grow*ldc + gcol);
      ph[0] = __halves2bfloat162(hx,hy); ph[1] = __halves2bfloat162(hz,hw2);
      __nv_bfloat162* pl = (__nv_bfloat162*)(Clo + (size_t)grow*ldc + gcol);
      pl[0] = __halves2bfloat162(lx,ly); pl[1] = __halves2bfloat162(lz,lw2);
    } else {
      if (gcol < Nreal)
        *(float4*)(C + (size_t)grow*ldc + gcol) = make_float4(vx,vy,vz,vw);
    }
  }
}

// ---------------- weight prep: transpose + bf16 hi/lo split ----------------
__global__ void prep_inw(const float* __restrict__ in_w){
  int idx = blockIdx.x*256 + threadIdx.x;
  int l = idx / (NPAD_IN*DM); int rem = idx % (NPAD_IN*DM);
  int n = rem / DM, k = rem % DM;
  float v = (n < DINPROJ) ? in_w[((size_t)l*DM + k)*DINPROJ + n] : 0.f;
  bf16 h, lo; split2(v, h, lo);
  g_inwh[idx] = h; g_inwl[idx] = lo;
}
__global__ void prep_outw(const float* __restrict__ out_w){
  int idx = blockIdx.x*256 + threadIdx.x;
  int l = idx / (DM*DINNER); int rem = idx % (DM*DINNER);
  int n = rem / DINNER, k = rem % DINNER;
  float v = out_w[((size_t)l*DINNER + k)*DM + n];
  bf16 h, lo; split2(v, h, lo);
  g_owh[idx] = h; g_owl[idx] = lo;
}
__global__ void prep_w2(const float* __restrict__ w2){
  int idx = blockIdx.x*256 + threadIdx.x;
  float v = w2[idx];
  bf16 h, lo; split2(v, h, lo);
  g_w2h[idx] = h; g_w2l[idx] = lo;
}

// ---------------- stem conv1: 3x3 SAME, 3->128, BN+GELU ----------------
__global__ __launch_bounds__(128) void conv1_kernel(const float* __restrict__ x,
    const float* __restrict__ w, const float* __restrict__ g1, const float* __restrict__ b1)
{
  __shared__ float swv[C1*27];
  __shared__ float sg[C1], sb[C1];
  int xx = threadIdx.x, y = blockIdx.x, b = blockIdx.y;
  for (int i=xx;i<C1*27;i+=128) swv[i]=w[i];
  sg[xx]=g1[xx]; sb[xx]=b1[xx];
  __syncthreads();
  float in[27];
  int q=0;
  #pragma unroll
  for (int ci=0;ci<3;ci++)
    #pragma unroll
    for (int ky=0;ky<3;ky++){
      int iy=y+ky-1;
      #pragma unroll
      for (int kx=0;kx<3;kx++){
        int ix=xx+kx-1;
        in[q++] = (iy>=0 && iy<HWD && ix>=0 && ix<HWD) ? x[((b*3+ci)*HWD+iy)*HWD+ix] : 0.f;
      }
    }
  for (int co=0;co<C1;co++){
    float acc=0.f;
    #pragma unroll
    for (int t=0;t<27;t++) acc += in[t]*swv[co*27+t];
    float v = acc*sg[co]+sb[co];
    g_h1[(((size_t)b*C1+co)*HWD+y)*HWD+xx] = geluf(v);
  }
}

// ---------------- im2col + bf16 hi/lo split ----------------
__global__ void im2col_split(){
  size_t idx = (size_t)blockIdx.x*256 + threadIdx.x;
  int k = (int)(idx & 2047); size_t row = idx >> 11;
  int b = (int)(row >> 10); int s = (int)(row & 1023); int y = s >> 5; int xq = s & 31;
  int ci = k >> 4, ky = (k>>2)&3, kx = k&3;
  float v = g_h1[(((size_t)b*C1+ci)*HWD + y*4+ky)*HWD + xq*4+kx];
  bf16 h, lo; split2(v, h, lo);
  g_imh[idx] = h; g_iml[idx] = lo;
}

// ---------------- depthwise causal conv1d (width 4) + silu ----------------
__global__ void dwconv_kernel(const float* __restrict__ cw, const float* __restrict__ cb, int layer){
  int idx = blockIdx.x*256 + threadIdx.x;
  int c = idx % CONVDIM; int row = idx / CONVDIM;
  int l = row & 1023, b = row >> 10;
  const float* wp = cw + (layer*CONVDIM + c)*4;
  float acc = cb[layer*CONVDIM + c];
  #pragma unroll
  for (int k=0;k<4;k++){
    int ls = l + k - 3;
    if (ls >= 0) acc += g_zx[((size_t)(b<<10)+ls)*DINPROJ + DINNER + c] * wp[k];
  }
  g_xbc[(size_t)row*CONVDIM + c] = siluf(acc);
}

// ---------------- dt/dA ----------------
__global__ void dtda_kernel(const float* __restrict__ dt_bias, const float* __restrict__ A_log, int layer){
  int idx = blockIdx.x*256+threadIdx.x;
  int h = idx & 7; int row = idx >> 3;
  float raw = g_zx[(size_t)row*DINPROJ + 1056 + h] + dt_bias[layer*8+h];
  float dt = (raw > 20.f) ? raw : log1pf(expf(raw));
  float dA = expf(-expf(A_log[layer*8+h])*dt);
  g_dtv[row*8+h] = dt;
  int l = row & 1023, b = row >> 10;
  g_dA[(size_t)(b*8+h)*LSEQ + l] = dA;
}

// ---------------- scan pass 1 ----------------
__global__ __launch_bounds__(64) void scan1_kernel(){
  __shared__ float sxdt[QCH][HEADDIM];
  __shared__ float sB[QCH][DSTATE];
  __shared__ float sC[QCH][DSTATE];
  __shared__ float sdA[QCH];
  int tid = threadIdx.x;
  int c = blockIdx.x & 15, h = (blockIdx.x>>4)&7, b = blockIdx.x>>7;
  for (int s=0;s<QCH;s++){
    int l = c*QCH+s; size_t row = (size_t)b*LSEQ + l;
    float dtv = g_dtv[row*NHEADS + h];
    sxdt[s][tid] = g_xbc[row*CONVDIM + h*HEADDIM + tid] * dtv;
    if (tid < DSTATE) sB[s][tid] = g_xbc[row*CONVDIM + DINNER + tid];
    else if (tid < 2*DSTATE) sC[s][tid-DSTATE] = g_xbc[row*CONVDIM + DINNER + DSTATE + (tid-DSTATE)];
    else if (tid == 32) sdA[s] = g_dA[(size_t)(b*NHEADS+h)*LSEQ + l];
  }
  __syncthreads();
  if (tid == 0){
    float r = 1.f;
    for (int s=0;s<QCH;s++){ r *= sdA[s]; g_cdA[(size_t)(b*NHEADS+h)*LSEQ + c*QCH + s] = r; }
  }
  float hr[DSTATE];
  #pragma unroll
  for (int n=0;n<DSTATE;n++) hr[n]=0.f;
  for (int s=0;s<QCH;s++){
    float dAv = sdA[s];
    float xv = sxdt[s][tid];
    float Bv[DSTATE], Cv[DSTATE];
    *(float4*)&Bv[0]  = *(const float4*)&sB[s][0];
    *(float4*)&Bv[4]  = *(const float4*)&sB[s][4];
    *(float4*)&Bv[8]  = *(const float4*)&sB[s][8];
    *(float4*)&Bv[12] = *(const float4*)&sB[s][12];
    *(float4*)&Cv[0]  = *(const float4*)&sC[s][0];
    *(float4*)&Cv[4]  = *(const float4*)&sC[s][4];
    *(float4*)&Cv[8]  = *(const float4*)&sC[s][8];
    *(float4*)&Cv[12] = *(const float4*)&sC[s][12];
    float y = 0.f;
    #pragma unroll
    for (int n=0;n<DSTATE;n++){
      hr[n] = hr[n]*dAv + xv*Bv[n];
      y += hr[n]*Cv[n];
    }
    size_t row = (size_t)b*LSEQ + c*QCH + s;
    g_ybuf[row*DINNER + h*HEADDIM + tid] = y;
  }
  size_t base = ((size_t)(b*NHEADS+h)*NCHUNK + c)*1024 + tid*DSTATE;
  #pragma unroll
  for (int n=0;n<DSTATE;n++) g_S[base+n] = hr[n];
}

// ---------------- scan pass 2 ----------------
__global__ __launch_bounds__(1024) void scan2_kernel(){
  int bh = blockIdx.x; int tid = threadIdx.x;
  float hprev = 0.f;
  for (int c=0;c<NCHUNK;c++){
    size_t base = ((size_t)bh*NCHUNK + c)*1024;
    g_hs[base + tid] = hprev;
    float Ac = g_cdA[(size_t)bh*LSEQ + c*QCH + QCH-1];
    hprev = hprev*Ac + g_S[base + tid];
  }
}

// ---------------- scan pass 3 ----------------
__global__ __launch_bounds__(256) void scan3_kernel(const float* __restrict__ Dskip, int layer){
  __shared__ float sCc[QCH*DSTATE];
  __shared__ float scd[QCH];
  int tid = threadIdx.x;
  int c = blockIdx.x & 15, h = (blockIdx.x>>4)&7, b = blockIdx.x>>7;
  for (int k=tid;k<QCH*DSTATE;k+=256){
    int s = k>>4, n = k&15;
    sCc[k] = g_xbc[((size_t)b*LSEQ + c*QCH + s)*CONVDIM + DINNER + DSTATE + n];
  }
  if (tid < QCH) scd[tid] = g_cdA[(size_t)(b*NHEADS+h)*LSEQ + c*QCH + tid];
  __syncthreads();
  int tg = tid >> 6, p = tid & 63;
  float hreg[DSTATE];
  size_t hbase = ((size_t)(b*NHEADS+h)*NCHUNK + c)*1024 + p*DSTATE;
  #pragma unroll
  for (int n=0;n<DSTATE;n++) hreg[n] = g_hs[hbase+n];
  float Dh = Dskip[layer*NHEADS+h];
  for (int t=tg*16; t<tg*16+16; t++){
    size_t row = (size_t)b*LSEQ + c*QCH + t;
    float acc = 0.f;
    #pragma unroll
    for (int n=0;n<DSTATE;n++) acc += sCc[t*DSTATE+n]*hreg[n];
    float xs = g_xbc[row*CONVDIM + h*HEADDIM + p];
    size_t yi = row*DINNER + h*HEADDIM + p;
    g_ybuf[yi] += scd[t]*acc + xs*Dh;
  }
}

// ---------------- gate + RMS-norm -> bf16 hi/lo ----------------
__global__ __launch_bounds__(128) void gate_kernel(const float* __restrict__ rms_w, int layer){
  __shared__ float sred[32];
  size_t row = blockIdx.x;
  int tid = threadIdx.x;
  float v[4]; float ss = 0.f;
  #pragma unroll
  for (int j=0;j<4;j++){
    int d = tid + j*128;
    float z = g_zx[row*DINPROJ + d];
    float yv = g_ybuf[row*DINNER + d];
    float g = yv * siluf(z);
    v[j]=g; ss += g*g;
  }
  ss = blockReduceSum(ss, sred);
  float rstd = rsqrtf(ss*(1.0f/DINNER) + EPSV);
  #pragma unroll
  for (int j=0;j<4;j++){
    int d = tid + j*128;
    float o = v[j]*rstd*rms_w[layer*DINNER + d];
    bf16 h, lo; split2(o, h, lo);
    g_gah[row*DINNER + d] = h;
    g_gal[row*DINNER + d] = lo;
  }
}

// ---------------- residual + LayerNorm -> tok fp32 + bf16 hi/lo ----------------
__global__ __launch_bounds__(256) void lnres_kernel(const float* __restrict__ lg, const float* __restrict__ lb, int layer){
  __shared__ float sred[32];
  size_t row = blockIdx.x; int d = threadIdx.x;
  float v = g_mproj[row*DM + d] + g_tok[row*DM + d];
  float mean = blockReduceSum(v, sred) * (1.0f/DM);
  float dv = v - mean;
  float var = blockReduceSum(dv*dv, sred) * (1.0f/DM);
  float o = dv*rsqrtf(var+EPSV)*lg[layer*DM+d] + lb[layer*DM+d];
  g_tok[row*DM + d] = o;
  bf16 h, lo; split2(o, h, lo);
  g_th[row*DM + d] = h;
  g_tl[row*DM + d] = lo;
}

// ---------------- mean-pool + LN + head ----------------
__global__ __launch_bounds__(256) void head_kernel(const float* __restrict__ hg, const float* __restrict__ hb,
    const float* __restrict__ hw, const float* __restrict__ hbias, float* __restrict__ out){
  __shared__ float sred[32];
  __shared__ float sn[DM];
  int b = blockIdx.x, d = threadIdx.x;
  float s=0.f;
  for (int l=0;l<LSEQ;l++) s += g_tok[((size_t)b*LSEQ+l)*DM + d];
  float pooled = s*(1.0f/LSEQ);
  float mean = blockReduceSum(pooled, sred)*(1.0f/DM);
  float dv = pooled-mean;
  float var = blockReduceSum(dv*dv, sred)*(1.0f/DM);
  sn[d] = dv*rsqrtf(var+EPSV)*hg[d]+hb[d];
  __syncthreads();
  if (d < 10){
    float acc = hbias[d];
    for (int k=0;k<DM;k++) acc += sn[k]*hw[k*10+d];
    out[b*10+d] = acc;
  }
}

// ---------------- host launcher ----------------
extern "C" void kernel_launch(void* const* d_in, const int* in_sizes, int n_in,
                              void* d_out, int out_size)
{
  const float* x       = (const float*)d_in[0];
  const float* w1      = (const float*)d_in[1];
  const float* sg1     = (const float*)d_in[2];
  const float* sb1     = (const float*)d_in[3];
  const float* w2      = (const float*)d_in[4];
  const float* sg2     = (const float*)d_in[5];
  const float* sb2     = (const float*)d_in[6];
  const float* in_w    = (const float*)d_in[7];
  const float* conv_w  = (const float*)d_in[8];
  const float* conv_b  = (const float*)d_in[9];
  const float* dt_bias = (const float*)d_in[10];
  const float* A_log   = (const float*)d_in[11];
  const float* D_skip  = (const float*)d_in[12];
  const float* rms_w   = (const float*)d_in[13];
  const float* out_w   = (const float*)d_in[14];
  const float* ln_g    = (const float*)d_in[15];
  const float* ln_b    = (const float*)d_in[16];
  const float* hg      = (const float*)d_in[17];
  const float* hb      = (const float*)d_in[18];
  const float* hw      = (const float*)d_in[19];
  const float* hbias   = (const float*)d_in[20];
  float* out = (float*)d_out;

  cudaFuncSetAttribute(mmagemm_kernel, cudaFuncAttributeMaxDynamicSharedMemorySize, MMG_SMEM);

  void *p;
  cudaGetSymbolAddress(&p, g_imh);  bf16* p_imh = (bf16*)p;
  cudaGetSymbolAddress(&p, g_iml);  bf16* p_iml = (bf16*)p;
  cudaGetSymbolAddress(&p, g_w2h);  bf16* p_w2h = (bf16*)p;
  cudaGetSymbolAddress(&p, g_w2l);  bf16* p_w2l = (bf16*)p;
  cudaGetSymbolAddress(&p, g_tok);  float* p_tok = (float*)p;
  cudaGetSymbolAddress(&p, g_th);   bf16* p_th = (bf16*)p;
  cudaGetSymbolAddress(&p, g_tl);   bf16* p_tl = (bf16*)p;
  cudaGetSymbolAddress(&p, g_inwh); bf16* p_inwh = (bf16*)p;
  cudaGetSymbolAddress(&p, g_inwl); bf16* p_inwl = (bf16*)p;
  cudaGetSymbolAddress(&p, g_owh);  bf16* p_owh = (bf16*)p;
  cudaGetSymbolAddress(&p, g_owl);  bf16* p_owl = (bf16*)p;
  cudaGetSymbolAddress(&p, g_zx);   float* p_zx = (float*)p;
  cudaGetSymbolAddress(&p, g_gah);  bf16* p_gah = (bf16*)p;
  cudaGetSymbolAddress(&p, g_gal);  bf16* p_gal = (bf16*)p;
  cudaGetSymbolAddress(&p, g_mproj);float* p_m = (float*)p;

  conv1_kernel<<<dim3(HWD,BATCH),128>>>(x, w1, sg1, sb1);
  prep_inw<<<(4*NPAD_IN*DM)/256,256>>>(in_w);
  prep_outw<<<(4*DM*DINNER)/256,256>>>(out_w);
  prep_w2<<<(256*2048)/256,256>>>(w2);
  im2col_split<<<65536,256>>>();

  mmagemm_kernel<<<dim3(2,64),256,MMG_SMEM>>>(p_imh, p_iml, p_w2h, p_w2l,
      p_tok, 2048, 256, 256, 1, sg2, sb2, p_th, p_tl);

  for (int i=0;i<4;i++){
    mmagemm_kernel<<<dim3(9,64),256,MMG_SMEM>>>(p_th, p_tl,
        p_inwh + (size_t)i*NPAD_IN*DM, p_inwl + (size_t)i*NPAD_IN*DM,
        p_zx, DM, DINPROJ, DINPROJ, 0, (const float*)0, (const float*)0, (bf16*)0, (bf16*)0);
    dwconv_kernel<<<(NROWS*CONVDIM)/256,256>>>(conv_w, conv_b, i);
    dtda_kernel<<<(NROWS*NHEADS)/256,256>>>(dt_bias, A_log, i);
    scan1_kernel<<<1024,64>>>();
    scan2_kernel<<<64,1024>>>();
    scan3_kernel<<<1024,256>>>(D_skip, i);
    gate_kernel<<<NROWS,128>>>(rms_w, i);
    mmagemm_kernel<<<dim3(2,64),256,MMG_SMEM>>>(p_gah, p_gal,
        p_owh + (size_t)i*DM*DINNER, p_owl + (size_t)i*DM*DINNER,
        p_m, DINNER, DM, DM, 0, (const float*)0, (const float*)0, (bf16*)0, (bf16*)0);
    lnres_kernel<<<NROWS,256>>>(ln_g, ln_b, i);
  }

  head_kernel<<<BATCH,256>>>(hg, hb, hw, hbias, out);
}

// round 4
// speedup vs baseline: 2.1741x; 1.9740x over previous
#include <cuda_runtime.h>
#include <cuda_fp16.h>
#include <math.h>
#include <stdint.h>

#define BATCH 8
#define HWD 128
#define C1 128
#define DM 256
#define LSEQ 1024
#define NROWS (BATCH*LSEQ)
#define DSTATE 16
#define HEADDIM 64
#define DINNER 512
#define NHEADS 8
#define CONVDIM 544
#define DINPROJ 1064
#define NPAD_IN 1152
#define NCHUNK 16
#define QCH 64
#define EPSV 1e-5f

typedef __half fp16;

// ---------------- scratch (device globals) ----------------
__device__ float g_h1[(size_t)BATCH*C1*HWD*HWD];
__device__ fp16  g_imh[(size_t)NROWS*2048];
__device__ fp16  g_w2h[256*2048];
__device__ float g_tok[NROWS*DM];
__device__ fp16  g_th[NROWS*DM];
__device__ fp16  g_inwh[4*NPAD_IN*DM];
__device__ fp16  g_owh[4*DM*DINNER];
__device__ float g_zx[(size_t)NROWS*DINPROJ];
__device__ float g_xbc[(size_t)NROWS*CONVDIM];
__device__ float g_dtv[NROWS*NHEADS];
__device__ float g_dA[NROWS*NHEADS];
__device__ float g_cdA[NROWS*NHEADS];
__device__ float g_ybuf[(size_t)NROWS*DINNER];
__device__ fp16  g_gah[(size_t)NROWS*DINNER];
__device__ float g_S[BATCH*NHEADS*NCHUNK*HEADDIM*DSTATE];
__device__ float g_hs[BATCH*NHEADS*NCHUNK*HEADDIM*DSTATE];
__device__ float g_mproj[NROWS*DM];
__device__ float g_pooled[BATCH*DM];

__device__ __forceinline__ float geluf(float t){ return 0.5f*t*(1.0f+erff(t*0.70710678118654752f)); }
__device__ __forceinline__ float siluf(float t){ return t/(1.0f+expf(-t)); }

__device__ __forceinline__ float blockReduceSum(float v, float* sred){
  int lane = threadIdx.x & 31, wid = threadIdx.x >> 5;
  #pragma unroll
  for (int o=16;o>0;o>>=1) v += __shfl_xor_sync(0xffffffffu,v,o);
  if (lane==0) sred[wid]=v;
  __syncthreads();
  int nw = (blockDim.x+31)>>5;
  if (threadIdx.x < 32){
    float r = (threadIdx.x < nw) ? sred[threadIdx.x] : 0.f;
    #pragma unroll
    for (int o=16;o>0;o>>=1) r += __shfl_xor_sync(0xffffffffu,r,o);
    if (threadIdx.x==0) sred[0]=r;
  }
  __syncthreads();
  float r = sred[0];
  __syncthreads();
  return r;
}

// ---------------- mma/cp.async helpers (sm_80 baseline PTX) ----------------
__device__ __forceinline__ uint32_t smem_u32(const void* p){
  uint32_t a;
  asm("{ .reg .u64 t; cvta.to.shared.u64 t, %1; cvt.u32.u64 %0, t; }" : "=r"(a) : "l"(p));
  return a;
}
__device__ __forceinline__ void ldsm4(uint32_t& a0,uint32_t& a1,uint32_t& a2,uint32_t& a3, uint32_t addr){
  asm volatile("ldmatrix.sync.aligned.m8n8.x4.shared.b16 {%0,%1,%2,%3}, [%4];"
    : "=r"(a0),"=r"(a1),"=r"(a2),"=r"(a3) : "r"(addr));
}
__device__ __forceinline__ void ldsm2(uint32_t& a0,uint32_t& a1, uint32_t addr){
  asm volatile("ldmatrix.sync.aligned.m8n8.x2.shared.b16 {%0,%1}, [%2];"
    : "=r"(a0),"=r"(a1) : "r"(addr));
}
__device__ __forceinline__ void mma16816(float* d, uint32_t a0,uint32_t a1,uint32_t a2,uint32_t a3,
                                         uint32_t b0,uint32_t b1){
  asm volatile("mma.sync.aligned.m16n8k16.row.col.f32.f16.f16.f32 "
    "{%0,%1,%2,%3}, {%4,%5,%6,%7}, {%8,%9}, {%0,%1,%2,%3};"
    : "+f"(d[0]),"+f"(d[1]),"+f"(d[2]),"+f"(d[3])
    : "r"(a0),"r"(a1),"r"(a2),"r"(a3),"r"(b0),"r"(b1));
}
__device__ __forceinline__ void cpasync16(uint32_t s, const void* g){
  asm volatile("cp.async.cg.shared.global [%0], [%1], 16;" :: "r"(s), "l"(g) : "memory");
}
__device__ __forceinline__ void cpcommit(){ asm volatile("cp.async.commit_group;" ::: "memory"); }
__device__ __forceinline__ void cpwait0(){ asm volatile("cp.async.wait_group 0;" ::: "memory"); }
__device__ __forceinline__ void cpwait1(){ asm volatile("cp.async.wait_group 1;" ::: "memory"); }

// ---------------- fp16 HMMA GEMM: C[M,N] = A[M,K] @ B^T, single pass ----------------
// A: [M][K] fp16, B: [Npad][K] fp16. Block tile 128x128, K-chunk 64, cp.async double-buffer.
// 8 warps = 2(m) x 4(n); warp tile 64x32.
#define SPAD 72
#define SBUF 18432                    // 128*SPAD*2 bytes per matrix buffer
#define MMG_SMEM (4*SBUF)             // 73728 (two (A,B) buffers; also epilogue staging)
__global__ __launch_bounds__(256) void mmagemm_kernel(
    const fp16* __restrict__ A, const fp16* __restrict__ B,
    float* __restrict__ C, int K, int Nreal, int ldc, int epi,
    const float* __restrict__ eg, const float* __restrict__ eb,
    fp16* __restrict__ Cho)
{
  extern __shared__ char smem[];
  uint32_t sbase = smem_u32(smem);
  int tid = threadIdx.x, lane = tid & 31, wid = tid >> 5;
  int row0 = blockIdx.y<<7, col0 = blockIdx.x<<7;
  int warp_m = wid >> 2, warp_n = wid & 3;
  int m0w = warp_m*64, n0w = warp_n*32;

  int lr = tid >> 1, lh = tid & 1;
  const fp16* gA = A + (size_t)(row0+lr)*K + lh*32;
  const fp16* gB = B + (size_t)(col0+lr)*K + lh*32;
  uint32_t s_off = (uint32_t)(lr*SPAD + lh*32)*2;

  uint32_t a_ld = (uint32_t)((m0w + (lane&7) + ((lane>>3)&1)*8)*SPAD*2 + (lane>>4)*16);
  uint32_t b_ld = (uint32_t)((n0w + (lane&7))*SPAD*2 + ((lane>>3)&1)*16);

  float d[4][4][4];
  #pragma unroll
  for (int i=0;i<4;i++)
    #pragma unroll
    for (int j=0;j<4;j++)
      #pragma unroll
      for (int q=0;q<4;q++) d[i][j][q]=0.f;

  int NC = K>>6;
  // prefetch chunk 0
  {
    uint32_t sa = sbase + s_off, sb = sa + SBUF;
    #pragma unroll
    for (int j=0;j<4;j++) cpasync16(sa + j*16, gA + j*8);
    #pragma unroll
    for (int j=0;j<4;j++) cpasync16(sb + j*16, gB + j*8);
    cpcommit();
  }
  for (int c=0;c<NC;c++){
    if (c+1<NC){
      uint32_t sa = sbase + ((c+1)&1)*2*SBUF + s_off, sb = sa + SBUF;
      const fp16* pa = gA + (size_t)(c+1)*64;
      const fp16* pb = gB + (size_t)(c+1)*64;
      #pragma unroll
      for (int j=0;j<4;j++) cpasync16(sa + j*16, pa + j*8);
      #pragma unroll
      for (int j=0;j<4;j++) cpasync16(sb + j*16, pb + j*8);
      cpcommit();
      cpwait1();
    } else {
      cpwait0();
    }
    __syncthreads();
    uint32_t uA = sbase + (c&1)*2*SBUF;
    uint32_t uB = uA + SBUF;
    #pragma unroll
    for (int kk=0;kk<4;kk++){
      uint32_t b0[4], b1[4];
      #pragma unroll
      for (int j=0;j<4;j++)
        ldsm2(b0[j], b1[j], uB + b_ld + (uint32_t)(j*8*SPAD*2 + kk*32));
      #pragma unroll
      for (int i=0;i<4;i++){
        uint32_t a0,a1,a2,a3;
        ldsm4(a0,a1,a2,a3, uA + a_ld + (uint32_t)(i*16*SPAD*2 + kk*32));
        #pragma unroll
        for (int j=0;j<4;j++) mma16816(d[i][j], a0,a1,a2,a3, b0[j],b1[j]);
      }
    }
    __syncthreads();
  }

  // stage accums to smem, vectorized epilogue
  float* stg = (float*)smem;            // [128][132]
  #pragma unroll
  for (int i=0;i<4;i++){
    int r0 = m0w + i*16 + (lane>>2);
    #pragma unroll
    for (int j=0;j<4;j++){
      int c0 = n0w + j*8 + (lane&3)*2;
      *(float2*)&stg[r0*132 + c0]     = make_float2(d[i][j][0], d[i][j][1]);
      *(float2*)&stg[(r0+8)*132 + c0] = make_float2(d[i][j][2], d[i][j][3]);
    }
  }
  __syncthreads();

  #pragma unroll 1
  for (int q=0;q<16;q++){
    int e = q*256 + tid;
    int rr = e>>5, cc = (e&31)*4;
    float vx = stg[rr*132+cc+0], vy = stg[rr*132+cc+1];
    float vz = stg[rr*132+cc+2], vw = stg[rr*132+cc+3];
    int gcol = col0 + cc, grow = row0 + rr;
    if (epi==1){
      vx = geluf(vx*eg[gcol+0]+eb[gcol+0]);
      vy = geluf(vy*eg[gcol+1]+eb[gcol+1]);
      vz = geluf(vz*eg[gcol+2]+eb[gcol+2]);
      vw = geluf(vw*eg[gcol+3]+eb[gcol+3]);
      *(float4*)(C + (size_t)grow*ldc + gcol) = make_float4(vx,vy,vz,vw);
      __half2* ph = (__half2*)(Cho + (size_t)grow*ldc + gcol);
      ph[0] = __floats2half2_rn(vx,vy);
      ph[1] = __floats2half2_rn(vz,vw);
    } else {
      if (gcol < Nreal)
        *(float4*)(C + (size_t)grow*ldc + gcol) = make_float4(vx,vy,vz,vw);
    }
  }
}

// ---------------- weight prep: transpose + fp16 ----------------
__global__ void prep_inw(const float* __restrict__ in_w){
  int idx = blockIdx.x*256 + threadIdx.x;
  int l = idx / (NPAD_IN*DM); int rem = idx % (NPAD_IN*DM);
  int n = rem / DM, k = rem % DM;
  float v = (n < DINPROJ) ? in_w[((size_t)l*DM + k)*DINPROJ + n] : 0.f;
  g_inwh[idx] = __float2half(v);
}
__global__ void prep_outw(const float* __restrict__ out_w){
  int idx = blockIdx.x*256 + threadIdx.x;
  int l = idx / (DM*DINNER); int rem = idx % (DM*DINNER);
  int n = rem / DINNER, k = rem % DINNER;
  g_owh[idx] = __float2half(out_w[((size_t)l*DINNER + k)*DM + n]);
}
__global__ void prep_w2(const float* __restrict__ w2){
  int idx = blockIdx.x*256 + threadIdx.x;
  g_w2h[idx] = __float2half(w2[idx]);
}

// ---------------- stem conv1: 3x3 SAME, 3->128, BN+GELU ----------------
__global__ __launch_bounds__(128) void conv1_kernel(const float* __restrict__ x,
    const float* __restrict__ w, const float* __restrict__ g1, const float* __restrict__ b1)
{
  __shared__ float swv[C1*27];
  __shared__ float sg[C1], sb[C1];
  int xx = threadIdx.x, y = blockIdx.x, b = blockIdx.y;
  for (int i=xx;i<C1*27;i+=128) swv[i]=w[i];
  sg[xx]=g1[xx]; sb[xx]=b1[xx];
  __syncthreads();
  float in[27];
  int q=0;
  #pragma unroll
  for (int ci=0;ci<3;ci++)
    #pragma unroll
    for (int ky=0;ky<3;ky++){
      int iy=y+ky-1;
      #pragma unroll
      for (int kx=0;kx<3;kx++){
        int ix=xx+kx-1;
        in[q++] = (iy>=0 && iy<HWD && ix>=0 && ix<HWD) ? x[((b*3+ci)*HWD+iy)*HWD+ix] : 0.f;
      }
    }
  for (int co=0;co<C1;co++){
    float acc=0.f;
    #pragma unroll
    for (int t=0;t<27;t++) acc += in[t]*swv[co*27+t];
    float v = acc*sg[co]+sb[co];
    g_h1[(((size_t)b*C1+co)*HWD+y)*HWD+xx] = geluf(v);
  }
}

// ---------------- im2col -> fp16 ----------------
__global__ void im2col_split(){
  size_t idx = (size_t)blockIdx.x*256 + threadIdx.x;
  int k = (int)(idx & 2047); size_t row = idx >> 11;
  int b = (int)(row >> 10); int s = (int)(row & 1023); int y = s >> 5; int xq = s & 31;
  int ci = k >> 4, ky = (k>>2)&3, kx = k&3;
  g_imh[idx] = __float2half(g_h1[(((size_t)b*C1+ci)*HWD + y*4+ky)*HWD + xq*4+kx]);
}

// ---------------- depthwise causal conv1d (width 4) + silu ----------------
__global__ void dwconv_kernel(const float* __restrict__ cw, const float* __restrict__ cb, int layer){
  int idx = blockIdx.x*256 + threadIdx.x;
  int c = idx % CONVDIM; int row = idx / CONVDIM;
  int l = row & 1023, b = row >> 10;
  const float* wp = cw + (layer*CONVDIM + c)*4;
  float acc = cb[layer*CONVDIM + c];
  #pragma unroll
  for (int k=0;k<4;k++){
    int ls = l + k - 3;
    if (ls >= 0) acc += g_zx[((size_t)(b<<10)+ls)*DINPROJ + DINNER + c] * wp[k];
  }
  g_xbc[(size_t)row*CONVDIM + c] = siluf(acc);
}

// ---------------- dt/dA ----------------
__global__ void dtda_kernel(const float* __restrict__ dt_bias, const float* __restrict__ A_log, int layer){
  int idx = blockIdx.x*256+threadIdx.x;
  int h = idx & 7; int row = idx >> 3;
  float raw = g_zx[(size_t)row*DINPROJ + 1056 + h] + dt_bias[layer*8+h];
  float dt = (raw > 20.f) ? raw : log1pf(expf(raw));
  float dA = expf(-expf(A_log[layer*8+h])*dt);
  g_dtv[row*8+h] = dt;
  int l = row & 1023, b = row >> 10;
  g_dA[(size_t)(b*8+h)*LSEQ + l] = dA;
}

// ---------------- scan pass 1 ----------------
__global__ __launch_bounds__(64) void scan1_kernel(){
  __shared__ float sxdt[QCH][HEADDIM];
  __shared__ float sB[QCH][DSTATE];
  __shared__ float sC[QCH][DSTATE];
  __shared__ float sdA[QCH];
  int tid = threadIdx.x;
  int c = blockIdx.x & 15, h = (blockIdx.x>>4)&7, b = blockIdx.x>>7;
  for (int s=0;s<QCH;s++){
    int l = c*QCH+s; size_t row = (size_t)b*LSEQ + l;
    float dtv = g_dtv[row*NHEADS + h];
    sxdt[s][tid] = g_xbc[row*CONVDIM + h*HEADDIM + tid] * dtv;
    if (tid < DSTATE) sB[s][tid] = g_xbc[row*CONVDIM + DINNER + tid];
    else if (tid < 2*DSTATE) sC[s][tid-DSTATE] = g_xbc[row*CONVDIM + DINNER + DSTATE + (tid-DSTATE)];
    else if (tid == 32) sdA[s] = g_dA[(size_t)(b*NHEADS+h)*LSEQ + l];
  }
  __syncthreads();
  if (tid == 0){
    float r = 1.f;
    for (int s=0;s<QCH;s++){ r *= sdA[s]; g_cdA[(size_t)(b*NHEADS+h)*LSEQ + c*QCH + s] = r; }
  }
  float hr[DSTATE];
  #pragma unroll
  for (int n=0;n<DSTATE;n++) hr[n]=0.f;
  for (int s=0;s<QCH;s++){
    float dAv = sdA[s];
    float xv = sxdt[s][tid];
    float Bv[DSTATE], Cv[DSTATE];
    *(float4*)&Bv[0]  = *(const float4*)&sB[s][0];
    *(float4*)&Bv[4]  = *(const float4*)&sB[s][4];
    *(float4*)&Bv[8]  = *(const float4*)&sB[s][8];
    *(float4*)&Bv[12] = *(const float4*)&sB[s][12];
    *(float4*)&Cv[0]  = *(const float4*)&sC[s][0];
    *(float4*)&Cv[4]  = *(const float4*)&sC[s][4];
    *(float4*)&Cv[8]  = *(const float4*)&sC[s][8];
    *(float4*)&Cv[12] = *(const float4*)&sC[s][12];
    float y = 0.f;
    #pragma unroll
    for (int n=0;n<DSTATE;n++){
      hr[n] = hr[n]*dAv + xv*Bv[n];
      y += hr[n]*Cv[n];
    }
    size_t row = (size_t)b*LSEQ + c*QCH + s;
    g_ybuf[row*DINNER + h*HEADDIM + tid] = y;
  }
  size_t base = ((size_t)(b*NHEADS+h)*NCHUNK + c)*1024 + tid*DSTATE;
  #pragma unroll
  for (int n=0;n<DSTATE;n++) g_S[base+n] = hr[n];
}

// ---------------- scan pass 2 ----------------
__global__ __launch_bounds__(1024) void scan2_kernel(){
  int bh = blockIdx.x; int tid = threadIdx.x;
  float hprev = 0.f;
  for (int c=0;c<NCHUNK;c++){
    size_t base = ((size_t)bh*NCHUNK + c)*1024;
    g_hs[base + tid] = hprev;
    float Ac = g_cdA[(size_t)bh*LSEQ + c*QCH + QCH-1];
    hprev = hprev*Ac + g_S[base + tid];
  }
}

// ---------------- scan pass 3 ----------------
__global__ __launch_bounds__(256) void scan3_kernel(const float* __restrict__ Dskip, int layer){
  __shared__ float sCc[QCH*DSTATE];
  __shared__ float scd[QCH];
  int tid = threadIdx.x;
  int c = blockIdx.x & 15, h = (blockIdx.x>>4)&7, b = blockIdx.x>>7;
  for (int k=tid;k<QCH*DSTATE;k+=256){
    int s = k>>4, n = k&15;
    sCc[k] = g_xbc[((size_t)b*LSEQ + c*QCH + s)*CONVDIM + DINNER + DSTATE + n];
  }
  if (tid < QCH) scd[tid] = g_cdA[(size_t)(b*NHEADS+h)*LSEQ + c*QCH + tid];
  __syncthreads();
  int tg = tid >> 6, p = tid & 63;
  float hreg[DSTATE];
  size_t hbase = ((size_t)(b*NHEADS+h)*NCHUNK + c)*1024 + p*DSTATE;
  #pragma unroll
  for (int n=0;n<DSTATE;n++) hreg[n] = g_hs[hbase+n];
  float Dh = Dskip[layer*NHEADS+h];
  for (int t=tg*16; t<tg*16+16; t++){
    size_t row = (size_t)b*LSEQ + c*QCH + t;
    float acc = 0.f;
    #pragma unroll
    for (int n=0;n<DSTATE;n++) acc += sCc[t*DSTATE+n]*hreg[n];
    float xs = g_xbc[row*CONVDIM + h*HEADDIM + p];
    size_t yi = row*DINNER + h*HEADDIM + p;
    g_ybuf[yi] += scd[t]*acc + xs*Dh;
  }
}

// ---------------- gate + RMS-norm -> fp16 ----------------
__global__ __launch_bounds__(128) void gate_kernel(const float* __restrict__ rms_w, int layer){
  __shared__ float sred[32];
  size_t row = blockIdx.x;
  int tid = threadIdx.x;
  float v[4]; float ss = 0.f;
  #pragma unroll
  for (int j=0;j<4;j++){
    int d = tid + j*128;
    float z = g_zx[row*DINPROJ + d];
    float yv = g_ybuf[row*DINNER + d];
    float g = yv * siluf(z);
    v[j]=g; ss += g*g;
  }
  ss = blockReduceSum(ss, sred);
  float rstd = rsqrtf(ss*(1.0f/DINNER) + EPSV);
  #pragma unroll
  for (int j=0;j<4;j++){
    int d = tid + j*128;
    g_gah[row*DINNER + d] = __float2half(v[j]*rstd*rms_w[layer*DINNER + d]);
  }
}

// ---------------- residual + LayerNorm -> tok fp32 + fp16 ----------------
__global__ __launch_bounds__(256) void lnres_kernel(const float* __restrict__ lg, const float* __restrict__ lb, int layer){
  __shared__ float sred[32];
  size_t row = blockIdx.x; int d = threadIdx.x;
  float v = g_mproj[row*DM + d] + g_tok[row*DM + d];
  float mean = blockReduceSum(v, sred) * (1.0f/DM);
  float dv = v - mean;
  float var = blockReduceSum(dv*dv, sred) * (1.0f/DM);
  float o = dv*rsqrtf(var+EPSV)*lg[layer*DM+d] + lb[layer*DM+d];
  g_tok[row*DM + d] = o;
  g_th[row*DM + d] = __float2half(o);
}

// ---------------- grid-wide mean pool over L ----------------
__global__ __launch_bounds__(256) void pool_kernel(){
  __shared__ float s[256];
  int b = blockIdx.x >> 5, cg = blockIdx.x & 31;     // 32 col-groups of 8
  int colq = threadIdx.x & 7, lg = threadIdx.x >> 3; // 32 l-groups
  int col = cg*8 + colq;
  float acc = 0.f;
  for (int j=0;j<32;j++){
    int l = lg + j*32;
    acc += g_tok[((size_t)b*LSEQ + l)*DM + col];
  }
  s[threadIdx.x] = acc;
  __syncthreads();
  for (int off=16; off>0; off>>=1){
    if (lg < off) s[lg*8+colq] += s[(lg+off)*8+colq];
    __syncthreads();
  }
  if (lg == 0) g_pooled[b*DM + col] = s[colq]*(1.0f/LSEQ);
}

// ---------------- LN + head on pooled ----------------
__global__ __launch_bounds__(256) void head_kernel(const float* __restrict__ hg, const float* __restrict__ hb,
    const float* __restrict__ hw, const float* __restrict__ hbias, float* __restrict__ out){
  __shared__ float sred[32];
  __shared__ float sn[DM];
  int b = blockIdx.x, d = threadIdx.x;
  float pooled = g_pooled[b*DM + d];
  float mean = blockReduceSum(pooled, sred)*(1.0f/DM);
  float dv = pooled-mean;
  float var = blockReduceSum(dv*dv, sred)*(1.0f/DM);
  sn[d] = dv*rsqrtf(var+EPSV)*hg[d]+hb[d];
  __syncthreads();
  if (d < 10){
    float acc = hbias[d];
    for (int k=0;k<DM;k++) acc += sn[k]*hw[k*10+d];
    out[b*10+d] = acc;
  }
}

// ---------------- host launcher ----------------
extern "C" void kernel_launch(void* const* d_in, const int* in_sizes, int n_in,
                              void* d_out, int out_size)
{
  const float* x       = (const float*)d_in[0];
  const float* w1      = (const float*)d_in[1];
  const float* sg1     = (const float*)d_in[2];
  const float* sb1     = (const float*)d_in[3];
  const float* w2      = (const float*)d_in[4];
  const float* sg2     = (const float*)d_in[5];
  const float* sb2     = (const float*)d_in[6];
  const float* in_w    = (const float*)d_in[7];
  const float* conv_w  = (const float*)d_in[8];
  const float* conv_b  = (const float*)d_in[9];
  const float* dt_bias = (const float*)d_in[10];
  const float* A_log   = (const float*)d_in[11];
  const float* D_skip  = (const float*)d_in[12];
  const float* rms_w   = (const float*)d_in[13];
  const float* out_w   = (const float*)d_in[14];
  const float* ln_g    = (const float*)d_in[15];
  const float* ln_b    = (const float*)d_in[16];
  const float* hg      = (const float*)d_in[17];
  const float* hb      = (const float*)d_in[18];
  const float* hw      = (const float*)d_in[19];
  const float* hbias   = (const float*)d_in[20];
  float* out = (float*)d_out;

  cudaFuncSetAttribute(mmagemm_kernel, cudaFuncAttributeMaxDynamicSharedMemorySize, MMG_SMEM);

  void *p;
  cudaGetSymbolAddress(&p, g_imh);  fp16* p_imh = (fp16*)p;
  cudaGetSymbolAddress(&p, g_w2h);  fp16* p_w2h = (fp16*)p;
  cudaGetSymbolAddress(&p, g_tok);  float* p_tok = (float*)p;
  cudaGetSymbolAddress(&p, g_th);   fp16* p_th = (fp16*)p;
  cudaGetSymbolAddress(&p, g_inwh); fp16* p_inwh = (fp16*)p;
  cudaGetSymbolAddress(&p, g_owh);  fp16* p_owh = (fp16*)p;
  cudaGetSymbolAddress(&p, g_zx);   float* p_zx = (float*)p;
  cudaGetSymbolAddress(&p, g_gah);  fp16* p_gah = (fp16*)p;
  cudaGetSymbolAddress(&p, g_mproj);float* p_m = (float*)p;

  conv1_kernel<<<dim3(HWD,BATCH),128>>>(x, w1, sg1, sb1);
  prep_w2<<<(256*2048)/256,256>>>(w2);
  im2col_split<<<65536,256>>>();

  // conv2 GEMM (positioned near capture index for profiling)
  mmagemm_kernel<<<dim3(2,64),256,MMG_SMEM>>>(p_imh, p_w2h,
      p_tok, 2048, 256, 256, 1, sg2, sb2, p_th);

  prep_inw<<<(4*NPAD_IN*DM)/256,256>>>(in_w);
  prep_outw<<<(4*DM*DINNER)/256,256>>>(out_w);

  for (int i=0;i<4;i++){
    mmagemm_kernel<<<dim3(9,64),256,MMG_SMEM>>>(p_th,
        p_inwh + (size_t)i*NPAD_IN*DM,
        p_zx, DM, DINPROJ, DINPROJ, 0, (const float*)0, (const float*)0, (fp16*)0);
    dwconv_kernel<<<(NROWS*CONVDIM)/256,256>>>(conv_w, conv_b, i);
    dtda_kernel<<<(NROWS*NHEADS)/256,256>>>(dt_bias, A_log, i);
    scan1_kernel<<<1024,64>>>();
    scan2_kernel<<<64,1024>>>();
    scan3_kernel<<<1024,256>>>(D_skip, i);
    gate_kernel<<<NROWS,128>>>(rms_w, i);
    mmagemm_kernel<<<dim3(2,64),256,MMG_SMEM>>>(p_gah,
        p_owh + (size_t)i*DM*DINNER,
        p_m, DINNER, DM, DM, 0, (const float*)0, (const float*)0, (fp16*)0);
    lnres_kernel<<<NROWS,256>>>(ln_g, ln_b, i);
  }

  pool_kernel<<<BATCH*32,256>>>();
  head_kernel<<<BATCH,256>>>(hg, hb, hw, hbias, out);
}

// round 5
// speedup vs baseline: 2.4076x; 1.1074x over previous
#include <cuda_runtime.h>
#include <cuda_fp16.h>
#include <math.h>
#include <stdint.h>

#define BATCH 8
#define HWD 128
#define C1 128
#define DM 256
#define LSEQ 1024
#define NROWS (BATCH*LSEQ)
#define DSTATE 16
#define HEADDIM 64
#define DINNER 512
#define NHEADS 8
#define CONVDIM 544
#define DINPROJ 1064
#define NPAD_IN 1152
#define NCHUNK 16
#define QCH 64
#define EPSV 1e-5f

typedef __half fp16;

// ---------------- scratch (device globals) ----------------
__device__ fp16  g_imh[(size_t)NROWS*2048];
__device__ fp16  g_w2h[256*2048];
__device__ float g_tok[NROWS*DM];
__device__ fp16  g_th[NROWS*DM];
__device__ fp16  g_inwh[4*NPAD_IN*DM];
__device__ fp16  g_owh[4*DM*DINNER];
__device__ float g_zx[(size_t)NROWS*DINPROJ];
__device__ float g_xbc[(size_t)NROWS*CONVDIM];
__device__ float g_dtv[NROWS*NHEADS];
__device__ float g_dA[NROWS*NHEADS];
__device__ float g_cdA[NROWS*NHEADS];
__device__ float g_ybuf[(size_t)NROWS*DINNER];
__device__ fp16  g_gah[(size_t)NROWS*DINNER];
__device__ float g_S[BATCH*NHEADS*NCHUNK*HEADDIM*DSTATE];
__device__ float g_hs[BATCH*NHEADS*NCHUNK*HEADDIM*DSTATE];
__device__ float g_mproj[NROWS*DM];
__device__ float g_pooled[BATCH*DM];

__device__ __forceinline__ float geluf(float t){ return 0.5f*t*(1.0f+erff(t*0.70710678118654752f)); }
__device__ __forceinline__ float siluf(float t){ return t/(1.0f+expf(-t)); }

__device__ __forceinline__ float blockReduceSum(float v, float* sred){
  int lane = threadIdx.x & 31, wid = threadIdx.x >> 5;
  #pragma unroll
  for (int o=16;o>0;o>>=1) v += __shfl_xor_sync(0xffffffffu,v,o);
  if (lane==0) sred[wid]=v;
  __syncthreads();
  int nw = (blockDim.x+31)>>5;
  if (threadIdx.x < 32){
    float r = (threadIdx.x < nw) ? sred[threadIdx.x] : 0.f;
    #pragma unroll
    for (int o=16;o>0;o>>=1) r += __shfl_xor_sync(0xffffffffu,r,o);
    if (threadIdx.x==0) sred[0]=r;
  }
  __syncthreads();
  float r = sred[0];
  __syncthreads();
  return r;
}

// ---------------- mma/cp.async helpers ----------------
__device__ __forceinline__ uint32_t smem_u32(const void* p){
  uint32_t a;
  asm("{ .reg .u64 t; cvta.to.shared.u64 t, %1; cvt.u32.u64 %0, t; }" : "=r"(a) : "l"(p));
  return a;
}
__device__ __forceinline__ void ldsm4(uint32_t& a0,uint32_t& a1,uint32_t& a2,uint32_t& a3, uint32_t addr){
  asm volatile("ldmatrix.sync.aligned.m8n8.x4.shared.b16 {%0,%1,%2,%3}, [%4];"
    : "=r"(a0),"=r"(a1),"=r"(a2),"=r"(a3) : "r"(addr));
}
__device__ __forceinline__ void ldsm2(uint32_t& a0,uint32_t& a1, uint32_t addr){
  asm volatile("ldmatrix.sync.aligned.m8n8.x2.shared.b16 {%0,%1}, [%2];"
    : "=r"(a0),"=r"(a1) : "r"(addr));
}
__device__ __forceinline__ void mma16816(float* d, uint32_t a0,uint32_t a1,uint32_t a2,uint32_t a3,
                                         uint32_t b0,uint32_t b1){
  asm volatile("mma.sync.aligned.m16n8k16.row.col.f32.f16.f16.f32 "
    "{%0,%1,%2,%3}, {%4,%5,%6,%7}, {%8,%9}, {%0,%1,%2,%3};"
    : "+f"(d[0]),"+f"(d[1]),"+f"(d[2]),"+f"(d[3])
    : "r"(a0),"r"(a1),"r"(a2),"r"(a3),"r"(b0),"r"(b1));
}
__device__ __forceinline__ void cpasync16(uint32_t s, const void* g){
  asm volatile("cp.async.cg.shared.global [%0], [%1], 16;" :: "r"(s), "l"(g) : "memory");
}
__device__ __forceinline__ void cpcommit(){ asm volatile("cp.async.commit_group;" ::: "memory"); }
__device__ __forceinline__ void cpwait0(){ asm volatile("cp.async.wait_group 0;" ::: "memory"); }
__device__ __forceinline__ void cpwait1(){ asm volatile("cp.async.wait_group 1;" ::: "memory"); }

// ---------------- fp16 HMMA GEMM: C[M,N] = A[M,K] @ B^T ----------------
// Block tile 64x128, 8 warps = 2(m)x4(n), warp tile 32x32. K-chunk 64, double buffered.
#define SPAD 72
#define ABUF (64*SPAD*2)              // 9216
#define BBUF (128*SPAD*2)             // 18432
#define STAGEB (ABUF+BBUF)            // 27648 per stage
#define MMG_SMEM (2*STAGEB)           // 55296; epilogue staging 64*132*4=33792 fits
__global__ __launch_bounds__(256) void mmagemm_kernel(
    const fp16* __restrict__ A, const fp16* __restrict__ B,
    float* __restrict__ C, int K, int Nreal, int ldc, int epi,
    const float* __restrict__ eg, const float* __restrict__ eb,
    fp16* __restrict__ Cho)
{
  extern __shared__ char smem[];
  uint32_t sbase = smem_u32(smem);
  int tid = threadIdx.x, lane = tid & 31, wid = tid >> 5;
  int row0 = blockIdx.y<<6, col0 = blockIdx.x<<7;
  int warp_m = wid >> 2, warp_n = wid & 3;
  int m0w = warp_m*32, n0w = warp_n*32;

  // A load: 64 rows x 8 chunks(16B) = 512 ids; 2 per thread
  // B load: 128 rows x 8 chunks = 1024 ids; 4 per thread
  int a_r[2], a_c[2];
  #pragma unroll
  for (int j=0;j<2;j++){ int id = tid + j*256; a_r[j]=id>>3; a_c[j]=(id&7)*8; }
  int b_r[4], b_c[4];
  #pragma unroll
  for (int j=0;j<4;j++){ int id = tid + j*256; b_r[j]=id>>3; b_c[j]=(id&7)*8; }

  uint32_t a_ld = (uint32_t)((m0w + (lane&7) + ((lane>>3)&1)*8)*SPAD*2 + (lane>>4)*16);
  uint32_t b_ld = (uint32_t)((n0w + (lane&7))*SPAD*2 + ((lane>>3)&1)*16);

  float d[2][4][4];
  #pragma unroll
  for (int i=0;i<2;i++)
    #pragma unroll
    for (int j=0;j<4;j++)
      #pragma unroll
      for (int q=0;q<4;q++) d[i][j][q]=0.f;

  int NC = K>>6;
  {
    uint32_t sa = sbase, sb = sbase + ABUF;
    #pragma unroll
    for (int j=0;j<2;j++) cpasync16(sa + (uint32_t)(a_r[j]*SPAD + a_c[j])*2,
                                    A + (size_t)(row0+a_r[j])*K + a_c[j]);
    #pragma unroll
    for (int j=0;j<4;j++) cpasync16(sb + (uint32_t)(b_r[j]*SPAD + b_c[j])*2,
                                    B + (size_t)(col0+b_r[j])*K + b_c[j]);
    cpcommit();
  }
  for (int c=0;c<NC;c++){
    if (c+1<NC){
      uint32_t sa = sbase + ((c+1)&1)*STAGEB, sb = sa + ABUF;
      int kof = (c+1)*64;
      #pragma unroll
      for (int j=0;j<2;j++) cpasync16(sa + (uint32_t)(a_r[j]*SPAD + a_c[j])*2,
                                      A + (size_t)(row0+a_r[j])*K + kof + a_c[j]);
      #pragma unroll
      for (int j=0;j<4;j++) cpasync16(sb + (uint32_t)(b_r[j]*SPAD + b_c[j])*2,
                                      B + (size_t)(col0+b_r[j])*K + kof + b_c[j]);
      cpcommit();
      cpwait1();
    } else {
      cpwait0();
    }
    __syncthreads();
    uint32_t uA = sbase + (c&1)*STAGEB;
    uint32_t uB = uA + ABUF;
    #pragma unroll
    for (int kk=0;kk<4;kk++){
      uint32_t b0[4], b1[4];
      #pragma unroll
      for (int j=0;j<4;j++)
        ldsm2(b0[j], b1[j], uB + b_ld + (uint32_t)(j*8*SPAD*2 + kk*32));
      #pragma unroll
      for (int i=0;i<2;i++){
        uint32_t x0,x1,x2,x3;
        ldsm4(x0,x1,x2,x3, uA + a_ld + (uint32_t)(i*16*SPAD*2 + kk*32));
        #pragma unroll
        for (int j=0;j<4;j++) mma16816(d[i][j], x0,x1,x2,x3, b0[j],b1[j]);
      }
    }
    __syncthreads();
  }

  // stage accums, vectorized epilogue
  float* stg = (float*)smem;            // [64][132]
  #pragma unroll
  for (int i=0;i<2;i++){
    int r0 = m0w + i*16 + (lane>>2);
    #pragma unroll
    for (int j=0;j<4;j++){
      int c0 = n0w + j*8 + (lane&3)*2;
      *(float2*)&stg[r0*132 + c0]     = make_float2(d[i][j][0], d[i][j][1]);
      *(float2*)&stg[(r0+8)*132 + c0] = make_float2(d[i][j][2], d[i][j][3]);
    }
  }
  __syncthreads();

  #pragma unroll 1
  for (int q=0;q<8;q++){
    int e = q*256 + tid;
    int rr = e>>5, cc = (e&31)*4;
    float vx = stg[rr*132+cc+0], vy = stg[rr*132+cc+1];
    float vz = stg[rr*132+cc+2], vw = stg[rr*132+cc+3];
    int gcol = col0 + cc, grow = row0 + rr;
    if (epi==1){
      vx = geluf(vx*eg[gcol+0]+eb[gcol+0]);
      vy = geluf(vy*eg[gcol+1]+eb[gcol+1]);
      vz = geluf(vz*eg[gcol+2]+eb[gcol+2]);
      vw = geluf(vw*eg[gcol+3]+eb[gcol+3]);
      *(float4*)(C + (size_t)grow*ldc + gcol) = make_float4(vx,vy,vz,vw);
      __half2* ph = (__half2*)(Cho + (size_t)grow*ldc + gcol);
      ph[0] = __floats2half2_rn(vx,vy);
      ph[1] = __floats2half2_rn(vz,vw);
    } else {
      if (gcol < Nreal)
        *(float4*)(C + (size_t)grow*ldc + gcol) = make_float4(vx,vy,vz,vw);
    }
  }
}

// ---------------- weight prep ----------------
__global__ void prep_inw(const float* __restrict__ in_w){
  int idx = blockIdx.x*256 + threadIdx.x;
  int l = idx / (NPAD_IN*DM); int rem = idx % (NPAD_IN*DM);
  int n = rem / DM, k = rem % DM;
  float v = (n < DINPROJ) ? in_w[((size_t)l*DM + k)*DINPROJ + n] : 0.f;
  g_inwh[idx] = __float2half(v);
}
__global__ void prep_outw(const float* __restrict__ out_w){
  int idx = blockIdx.x*256 + threadIdx.x;
  int l = idx / (DM*DINNER); int rem = idx % (DM*DINNER);
  int n = rem / DINNER, k = rem % DINNER;
  g_owh[idx] = __float2half(out_w[((size_t)l*DINNER + k)*DM + n]);
}
__global__ void prep_w2(const float* __restrict__ w2){
  int idx = blockIdx.x*256 + threadIdx.x;
  g_w2h[idx] = __float2half(w2[idx]);
}

// ---------------- fused stem conv1 (3x3 SAME, BN+GELU) -> im2col fp16 ----------------
// block = (y_img, b); 128 threads over x_img. Output scattered via smem stage.
__global__ __launch_bounds__(128) void conv1_kernel(const float* __restrict__ x,
    const float* __restrict__ w, const float* __restrict__ g1, const float* __restrict__ b1)
{
  __shared__ float swv[C1*27];
  __shared__ float sg[C1], sb[C1];
  __shared__ fp16 sstage[32][516];     // 32 token-rows x (128 ci x 4 kx)
  int xx = threadIdx.x, y = blockIdx.x, b = blockIdx.y;
  for (int i=xx;i<C1*27;i+=128) swv[i]=w[i];
  sg[xx]=g1[xx]; sb[xx]=b1[xx];
  __syncthreads();
  float in[27];
  int q=0;
  #pragma unroll
  for (int ci=0;ci<3;ci++)
    #pragma unroll
    for (int ky=0;ky<3;ky++){
      int iy=y+ky-1;
      #pragma unroll
      for (int kx=0;kx<3;kx++){
        int ix=xx+kx-1;
        in[q++] = (iy>=0 && iy<HWD && ix>=0 && ix<HWD) ? x[((b*3+ci)*HWD+iy)*HWD+ix] : 0.f;
      }
    }
  int srow = xx>>2, scol = xx&3;
  for (int co=0;co<C1;co++){
    float acc=0.f;
    #pragma unroll
    for (int t=0;t<27;t++) acc += in[t]*swv[co*27+t];
    sstage[srow][co*4+scol] = __float2half(geluf(acc*sg[co]+sb[co]));
  }
  __syncthreads();
  // write out: 32 rows x 128 ci chunks of 4 fp16 (8B)
  int ky = y & 3;
  size_t rowbase = (size_t)b*LSEQ + (size_t)(y>>2)*32;
  #pragma unroll 4
  for (int t=0;t<32;t++){
    int id = xx + t*128;           // 0..4095
    int r = id >> 7, ci = id & 127;
    *(uint2*)(g_imh + (rowbase + r)*2048 + ci*16 + ky*4) = *(uint2*)&sstage[r][ci*4];
  }
}

// ---------------- fused depthwise conv1d + silu + dt/dA ----------------
#define FUSED_C (CONVDIM+NHEADS)     // 552
__global__ void dwdt_kernel(const float* __restrict__ cw, const float* __restrict__ cb,
                            const float* __restrict__ dt_bias, const float* __restrict__ A_log, int layer){
  int idx = blockIdx.x*256 + threadIdx.x;
  if (idx >= NROWS*FUSED_C) return;
  int c = idx % FUSED_C; int row = idx / FUSED_C;
  int l = row & 1023, b = row >> 10;
  if (c < CONVDIM){
    const float* wp = cw + (layer*CONVDIM + c)*4;
    float acc = cb[layer*CONVDIM + c];
    #pragma unroll
    for (int k=0;k<4;k++){
      int ls = l + k - 3;
      if (ls >= 0) acc += g_zx[((size_t)(b<<10)+ls)*DINPROJ + DINNER + c] * wp[k];
    }
    g_xbc[(size_t)row*CONVDIM + c] = siluf(acc);
  } else {
    int h = c - CONVDIM;
    float raw = g_zx[(size_t)row*DINPROJ + 1056 + h] + dt_bias[layer*8+h];
    float dt = (raw > 20.f) ? raw : log1pf(expf(raw));
    float dA = expf(-expf(A_log[layer*8+h])*dt);
    g_dtv[row*8+h] = dt;
    g_dA[(size_t)(b*8+h)*LSEQ + l] = dA;
  }
}

// ---------------- scan pass 1 ----------------
__global__ __launch_bounds__(64) void scan1_kernel(){
  __shared__ float sxdt[QCH][HEADDIM];
  __shared__ float sB[QCH][DSTATE];
  __shared__ float sC[QCH][DSTATE];
  __shared__ float sdA[QCH];
  int tid = threadIdx.x;
  int c = blockIdx.x & 15, h = (blockIdx.x>>4)&7, b = blockIdx.x>>7;
  for (int s=0;s<QCH;s++){
    int l = c*QCH+s; size_t row = (size_t)b*LSEQ + l;
    float dtv = g_dtv[row*NHEADS + h];
    sxdt[s][tid] = g_xbc[row*CONVDIM + h*HEADDIM + tid] * dtv;
    if (tid < DSTATE) sB[s][tid] = g_xbc[row*CONVDIM + DINNER + tid];
    else if (tid < 2*DSTATE) sC[s][tid-DSTATE] = g_xbc[row*CONVDIM + DINNER + DSTATE + (tid-DSTATE)];
    else if (tid == 32) sdA[s] = g_dA[(size_t)(b*NHEADS+h)*LSEQ + l];
  }
  __syncthreads();
  if (tid == 0){
    float r = 1.f;
    for (int s=0;s<QCH;s++){ r *= sdA[s]; g_cdA[(size_t)(b*NHEADS+h)*LSEQ + c*QCH + s] = r; }
  }
  float hr[DSTATE];
  #pragma unroll
  for (int n=0;n<DSTATE;n++) hr[n]=0.f;
  for (int s=0;s<QCH;s++){
    float dAv = sdA[s];
    float xv = sxdt[s][tid];
    float Bv[DSTATE], Cv[DSTATE];
    *(float4*)&Bv[0]  = *(const float4*)&sB[s][0];
    *(float4*)&Bv[4]  = *(const float4*)&sB[s][4];
    *(float4*)&Bv[8]  = *(const float4*)&sB[s][8];
    *(float4*)&Bv[12] = *(const float4*)&sB[s][12];
    *(float4*)&Cv[0]  = *(const float4*)&sC[s][0];
    *(float4*)&Cv[4]  = *(const float4*)&sC[s][4];
    *(float4*)&Cv[8]  = *(const float4*)&sC[s][8];
    *(float4*)&Cv[12] = *(const float4*)&sC[s][12];
    float y = 0.f;
    #pragma unroll
    for (int n=0;n<DSTATE;n++){
      hr[n] = hr[n]*dAv + xv*Bv[n];
      y += hr[n]*Cv[n];
    }
    size_t row = (size_t)b*LSEQ + c*QCH + s;
    g_ybuf[row*DINNER + h*HEADDIM + tid] = y;
  }
  size_t base = ((size_t)(b*NHEADS+h)*NCHUNK + c)*1024 + tid*DSTATE;
  #pragma unroll
  for (int n=0;n<DSTATE;n++) g_S[base+n] = hr[n];
}

// ---------------- scan pass 2 ----------------
__global__ __launch_bounds__(1024) void scan2_kernel(){
  int bh = blockIdx.x; int tid = threadIdx.x;
  float hprev = 0.f;
  for (int c=0;c<NCHUNK;c++){
    size_t base = ((size_t)bh*NCHUNK + c)*1024;
    g_hs[base + tid] = hprev;
    float Ac = g_cdA[(size_t)bh*LSEQ + c*QCH + QCH-1];
    hprev = hprev*Ac + g_S[base + tid];
  }
}

// ---------------- scan pass 3 ----------------
__global__ __launch_bounds__(256) void scan3_kernel(const float* __restrict__ Dskip, int layer){
  __shared__ float sCc[QCH*DSTATE];
  __shared__ float scd[QCH];
  int tid = threadIdx.x;
  int c = blockIdx.x & 15, h = (blockIdx.x>>4)&7, b = blockIdx.x>>7;
  for (int k=tid;k<QCH*DSTATE;k+=256){
    int s = k>>4, n = k&15;
    sCc[k] = g_xbc[((size_t)b*LSEQ + c*QCH + s)*CONVDIM + DINNER + DSTATE + n];
  }
  if (tid < QCH) scd[tid] = g_cdA[(size_t)(b*NHEADS+h)*LSEQ + c*QCH + tid];
  __syncthreads();
  int tg = tid >> 6, p = tid & 63;
  float hreg[DSTATE];
  size_t hbase = ((size_t)(b*NHEADS+h)*NCHUNK + c)*1024 + p*DSTATE;
  #pragma unroll
  for (int n=0;n<DSTATE;n++) hreg[n] = g_hs[hbase+n];
  float Dh = Dskip[layer*NHEADS+h];
  for (int t=tg*16; t<tg*16+16; t++){
    size_t row = (size_t)b*LSEQ + c*QCH + t;
    float acc = 0.f;
    #pragma unroll
    for (int n=0;n<DSTATE;n++) acc += sCc[t*DSTATE+n]*hreg[n];
    float xs = g_xbc[row*CONVDIM + h*HEADDIM + p];
    size_t yi = row*DINNER + h*HEADDIM + p;
    g_ybuf[yi] += scd[t]*acc + xs*Dh;
  }
}

// ---------------- gate + RMS-norm -> fp16 ----------------
__global__ __launch_bounds__(128) void gate_kernel(const float* __restrict__ rms_w, int layer){
  __shared__ float sred[32];
  size_t row = blockIdx.x;
  int tid = threadIdx.x;
  float v[4]; float ss = 0.f;
  #pragma unroll
  for (int j=0;j<4;j++){
    int d = tid + j*128;
    float z = g_zx[row*DINPROJ + d];
    float yv = g_ybuf[row*DINNER + d];
    float g = yv * siluf(z);
    v[j]=g; ss += g*g;
  }
  ss = blockReduceSum(ss, sred);
  float rstd = rsqrtf(ss*(1.0f/DINNER) + EPSV);
  #pragma unroll
  for (int j=0;j<4;j++){
    int d = tid + j*128;
    g_gah[row*DINNER + d] = __float2half(v[j]*rstd*rms_w[layer*DINNER + d]);
  }
}

// ---------------- residual + LayerNorm -> tok fp32 + fp16 ----------------
__global__ __launch_bounds__(256) void lnres_kernel(const float* __restrict__ lg, const float* __restrict__ lb, int layer){
  __shared__ float sred[32];
  size_t row = blockIdx.x; int d = threadIdx.x;
  float v = g_mproj[row*DM + d] + g_tok[row*DM + d];
  float mean = blockReduceSum(v, sred) * (1.0f/DM);
  float dv = v - mean;
  float var = blockReduceSum(dv*dv, sred) * (1.0f/DM);
  float o = dv*rsqrtf(var+EPSV)*lg[layer*DM+d] + lb[layer*DM+d];
  g_tok[row*DM + d] = o;
  g_th[row*DM + d] = __float2half(o);
}

// ---------------- grid-wide mean pool over L ----------------
__global__ __launch_bounds__(256) void pool_kernel(){
  __shared__ float s[256];
  int b = blockIdx.x >> 5, cg = blockIdx.x & 31;
  int colq = threadIdx.x & 7, lg = threadIdx.x >> 3;
  int col = cg*8 + colq;
  float acc = 0.f;
  for (int j=0;j<32;j++){
    int l = lg + j*32;
    acc += g_tok[((size_t)b*LSEQ + l)*DM + col];
  }
  s[threadIdx.x] = acc;
  __syncthreads();
  for (int off=16; off>0; off>>=1){
    if (lg < off) s[lg*8+colq] += s[(lg+off)*8+colq];
    __syncthreads();
  }
  if (lg == 0) g_pooled[b*DM + col] = s[colq]*(1.0f/LSEQ);
}

// ---------------- LN + head ----------------
__global__ __launch_bounds__(256) void head_kernel(const float* __restrict__ hg, const float* __restrict__ hb,
    const float* __restrict__ hw, const float* __restrict__ hbias, float* __restrict__ out){
  __shared__ float sred[32];
  __shared__ float sn[DM];
  int b = blockIdx.x, d = threadIdx.x;
  float pooled = g_pooled[b*DM + d];
  float mean = blockReduceSum(pooled, sred)*(1.0f/DM);
  float dv = pooled-mean;
  float var = blockReduceSum(dv*dv, sred)*(1.0f/DM);
  sn[d] = dv*rsqrtf(var+EPSV)*hg[d]+hb[d];
  __syncthreads();
  if (d < 10){
    float acc = hbias[d];
    for (int k=0;k<DM;k++) acc += sn[k]*hw[k*10+d];
    out[b*10+d] = acc;
  }
}

// ---------------- host launcher ----------------
extern "C" void kernel_launch(void* const* d_in, const int* in_sizes, int n_in,
                              void* d_out, int out_size)
{
  const float* x       = (const float*)d_in[0];
  const float* w1      = (const float*)d_in[1];
  const float* sg1     = (const float*)d_in[2];
  const float* sb1     = (const float*)d_in[3];
  const float* w2      = (const float*)d_in[4];
  const float* sg2     = (const float*)d_in[5];
  const float* sb2     = (const float*)d_in[6];
  const float* in_w    = (const float*)d_in[7];
  const float* conv_w  = (const float*)d_in[8];
  const float* conv_b  = (const float*)d_in[9];
  const float* dt_bias = (const float*)d_in[10];
  const float* A_log   = (const float*)d_in[11];
  const float* D_skip  = (const float*)d_in[12];
  const float* rms_w   = (const float*)d_in[13];
  const float* out_w   = (const float*)d_in[14];
  const float* ln_g    = (const float*)d_in[15];
  const float* ln_b    = (const float*)d_in[16];
  const float* hg      = (const float*)d_in[17];
  const float* hb      = (const float*)d_in[18];
  const float* hw      = (const float*)d_in[19];
  const float* hbias   = (const float*)d_in[20];
  float* out = (float*)d_out;

  cudaFuncSetAttribute(mmagemm_kernel, cudaFuncAttributeMaxDynamicSharedMemorySize, MMG_SMEM);

  void *p;
  cudaGetSymbolAddress(&p, g_imh);  fp16* p_imh = (fp16*)p;
  cudaGetSymbolAddress(&p, g_w2h);  fp16* p_w2h = (fp16*)p;
  cudaGetSymbolAddress(&p, g_tok);  float* p_tok = (float*)p;
  cudaGetSymbolAddress(&p, g_th);   fp16* p_th = (fp16*)p;
  cudaGetSymbolAddress(&p, g_inwh); fp16* p_inwh = (fp16*)p;
  cudaGetSymbolAddress(&p, g_owh);  fp16* p_owh = (fp16*)p;
  cudaGetSymbolAddress(&p, g_zx);   float* p_zx = (float*)p;
  cudaGetSymbolAddress(&p, g_gah);  fp16* p_gah = (fp16*)p;
  cudaGetSymbolAddress(&p, g_mproj);float* p_m = (float*)p;

  conv1_kernel<<<dim3(HWD,BATCH),128>>>(x, w1, sg1, sb1);
  prep_w2<<<(256*2048)/256,256>>>(w2);

  // conv2 GEMM: grid (2,128), 64-row tiles
  mmagemm_kernel<<<dim3(2,128),256,MMG_SMEM>>>(p_imh, p_w2h,
      p_tok, 2048, 256, 256, 1, sg2, sb2, p_th);

  prep_inw<<<(4*NPAD_IN*DM)/256,256>>>(in_w);
  prep_outw<<<(4*DM*DINNER)/256,256>>>(out_w);

  for (int i=0;i<4;i++){
    mmagemm_kernel<<<dim3(9,128),256,MMG_SMEM>>>(p_th,
        p_inwh + (size_t)i*NPAD_IN*DM,
        p_zx, DM, DINPROJ, DINPROJ, 0, (const float*)0, (const float*)0, (fp16*)0);
    dwdt_kernel<<<(NROWS*FUSED_C+255)/256,256>>>(conv_w, conv_b, dt_bias, A_log, i);
    scan1_kernel<<<1024,64>>>();
    scan2_kernel<<<64,1024>>>();
    scan3_kernel<<<1024,256>>>(D_skip, i);
    gate_kernel<<<NROWS,128>>>(rms_w, i);
    mmagemm_kernel<<<dim3(2,128),256,MMG_SMEM>>>(p_gah,
        p_owh + (size_t)i*DM*DINNER,
        p_m, DINNER, DM, DM, 0, (const float*)0, (const float*)0, (fp16*)0);
    lnres_kernel<<<NROWS,256>>>(ln_g, ln_b, i);
  }

  pool_kernel<<<BATCH*32,256>>>();
  head_kernel<<<BATCH,256>>>(hg, hb, hw, hbias, out);
}

// round 6
// speedup vs baseline: 2.9550x; 1.2274x over previous
#include <cuda_runtime.h>
#include <cuda_fp16.h>
#include <math.h>
#include <stdint.h>

#define BATCH 8
#define HWD 128
#define C1 128
#define DM 256
#define LSEQ 1024
#define NROWS (BATCH*LSEQ)
#define DSTATE 16
#define HEADDIM 64
#define DINNER 512
#define NHEADS 8
#define CONVDIM 544
#define DINPROJ 1064
#define NPAD_IN 1152
#define NCHUNK 16
#define QCH 64
#define EPSV 1e-5f

typedef __half fp16;

// ---------------- scratch (device globals) ----------------
__device__ fp16  g_imh[(size_t)NROWS*2048];
__device__ fp16  g_w2h[256*2048];
__device__ float g_tok[NROWS*DM];
__device__ fp16  g_th[NROWS*DM];
__device__ fp16  g_inwh[4*NPAD_IN*DM];
__device__ fp16  g_owh[4*DM*DINNER];
__device__ float g_zx[(size_t)NROWS*DINPROJ];
__device__ float g_xbc[(size_t)NROWS*CONVDIM];
__device__ float g_dtv[NROWS*NHEADS];
__device__ float g_dA[NROWS*NHEADS];
__device__ float g_ybuf[(size_t)NROWS*DINNER];
__device__ fp16  g_gah[(size_t)NROWS*DINNER];
__device__ float g_mproj[NROWS*DM];
__device__ float g_pooled[BATCH*DM];

__device__ __forceinline__ float geluf(float t){ return 0.5f*t*(1.0f+erff(t*0.70710678118654752f)); }
__device__ __forceinline__ float siluf(float t){ return t/(1.0f+expf(-t)); }

__device__ __forceinline__ float blockReduceSum(float v, float* sred){
  int lane = threadIdx.x & 31, wid = threadIdx.x >> 5;
  #pragma unroll
  for (int o=16;o>0;o>>=1) v += __shfl_xor_sync(0xffffffffu,v,o);
  if (lane==0) sred[wid]=v;
  __syncthreads();
  int nw = (blockDim.x+31)>>5;
  if (threadIdx.x < 32){
    float r = (threadIdx.x < nw) ? sred[threadIdx.x] : 0.f;
    #pragma unroll
    for (int o=16;o>0;o>>=1) r += __shfl_xor_sync(0xffffffffu,r,o);
    if (threadIdx.x==0) sred[0]=r;
  }
  __syncthreads();
  float r = sred[0];
  __syncthreads();
  return r;
}

// ---------------- mma/cp.async helpers ----------------
__device__ __forceinline__ uint32_t smem_u32(const void* p){
  uint32_t a;
  asm("{ .reg .u64 t; cvta.to.shared.u64 t, %1; cvt.u32.u64 %0, t; }" : "=r"(a) : "l"(p));
  return a;
}
__device__ __forceinline__ void ldsm4(uint32_t& a0,uint32_t& a1,uint32_t& a2,uint32_t& a3, uint32_t addr){
  asm volatile("ldmatrix.sync.aligned.m8n8.x4.shared.b16 {%0,%1,%2,%3}, [%4];"
    : "=r"(a0),"=r"(a1),"=r"(a2),"=r"(a3) : "r"(addr));
}
__device__ __forceinline__ void ldsm2(uint32_t& a0,uint32_t& a1, uint32_t addr){
  asm volatile("ldmatrix.sync.aligned.m8n8.x2.shared.b16 {%0,%1}, [%2];"
    : "=r"(a0),"=r"(a1) : "r"(addr));
}
__device__ __forceinline__ void mma16816(float* d, uint32_t a0,uint32_t a1,uint32_t a2,uint32_t a3,
                                         uint32_t b0,uint32_t b1){
  asm volatile("mma.sync.aligned.m16n8k16.row.col.f32.f16.f16.f32 "
    "{%0,%1,%2,%3}, {%4,%5,%6,%7}, {%8,%9}, {%0,%1,%2,%3};"
    : "+f"(d[0]),"+f"(d[1]),"+f"(d[2]),"+f"(d[3])
    : "r"(a0),"r"(a1),"r"(a2),"r"(a3),"r"(b0),"r"(b1));
}
__device__ __forceinline__ void cpasync16(uint32_t s, const void* g){
  asm volatile("cp.async.cg.shared.global [%0], [%1], 16;" :: "r"(s), "l"(g) : "memory");
}
__device__ __forceinline__ void cpcommit(){ asm volatile("cp.async.commit_group;" ::: "memory"); }
__device__ __forceinline__ void cpwait0(){ asm volatile("cp.async.wait_group 0;" ::: "memory"); }
__device__ __forceinline__ void cpwait1(){ asm volatile("cp.async.wait_group 1;" ::: "memory"); }

// ---------------- fp16 HMMA GEMM: C[M,N] = A[M,K] @ B^T ----------------
#define SPAD 72
#define ABUF (64*SPAD*2)
#define BBUF (128*SPAD*2)
#define STAGEB (ABUF+BBUF)
#define MMG_SMEM (2*STAGEB)
__global__ __launch_bounds__(256) void mmagemm_kernel(
    const fp16* __restrict__ A, const fp16* __restrict__ B,
    float* __restrict__ C, int K, int Nreal, int ldc, int epi,
    const float* __restrict__ eg, const float* __restrict__ eb,
    fp16* __restrict__ Cho)
{
  extern __shared__ char smem[];
  uint32_t sbase = smem_u32(smem);
  int tid = threadIdx.x, lane = tid & 31, wid = tid >> 5;
  int row0 = blockIdx.y<<6, col0 = blockIdx.x<<7;
  int warp_m = wid >> 2, warp_n = wid & 3;
  int m0w = warp_m*32, n0w = warp_n*32;

  int a_r[2], a_c[2];
  #pragma unroll
  for (int j=0;j<2;j++){ int id = tid + j*256; a_r[j]=id>>3; a_c[j]=(id&7)*8; }
  int b_r[4], b_c[4];
  #pragma unroll
  for (int j=0;j<4;j++){ int id = tid + j*256; b_r[j]=id>>3; b_c[j]=(id&7)*8; }

  uint32_t a_ld = (uint32_t)((m0w + (lane&7) + ((lane>>3)&1)*8)*SPAD*2 + (lane>>4)*16);
  uint32_t b_ld = (uint32_t)((n0w + (lane&7))*SPAD*2 + ((lane>>3)&1)*16);

  float d[2][4][4];
  #pragma unroll
  for (int i=0;i<2;i++)
    #pragma unroll
    for (int j=0;j<4;j++)
      #pragma unroll
      for (int q=0;q<4;q++) d[i][j][q]=0.f;

  int NC = K>>6;
  {
    uint32_t sa = sbase, sb = sbase + ABUF;
    #pragma unroll
    for (int j=0;j<2;j++) cpasync16(sa + (uint32_t)(a_r[j]*SPAD + a_c[j])*2,
                                    A + (size_t)(row0+a_r[j])*K + a_c[j]);
    #pragma unroll
    for (int j=0;j<4;j++) cpasync16(sb + (uint32_t)(b_r[j]*SPAD + b_c[j])*2,
                                    B + (size_t)(col0+b_r[j])*K + b_c[j]);
    cpcommit();
  }
  for (int c=0;c<NC;c++){
    if (c+1<NC){
      uint32_t sa = sbase + ((c+1)&1)*STAGEB, sb = sa + ABUF;
      int kof = (c+1)*64;
      #pragma unroll
      for (int j=0;j<2;j++) cpasync16(sa + (uint32_t)(a_r[j]*SPAD + a_c[j])*2,
                                      A + (size_t)(row0+a_r[j])*K + kof + a_c[j]);
      #pragma unroll
      for (int j=0;j<4;j++) cpasync16(sb + (uint32_t)(b_r[j]*SPAD + b_c[j])*2,
                                      B + (size_t)(col0+b_r[j])*K + kof + b_c[j]);
      cpcommit();
      cpwait1();
    } else {
      cpwait0();
    }
    __syncthreads();
    uint32_t uA = sbase + (c&1)*STAGEB;
    uint32_t uB = uA + ABUF;
    #pragma unroll
    for (int kk=0;kk<4;kk++){
      uint32_t b0[4], b1[4];
      #pragma unroll
      for (int j=0;j<4;j++)
        ldsm2(b0[j], b1[j], uB + b_ld + (uint32_t)(j*8*SPAD*2 + kk*32));
      #pragma unroll
      for (int i=0;i<2;i++){
        uint32_t x0,x1,x2,x3;
        ldsm4(x0,x1,x2,x3, uA + a_ld + (uint32_t)(i*16*SPAD*2 + kk*32));
        #pragma unroll
        for (int j=0;j<4;j++) mma16816(d[i][j], x0,x1,x2,x3, b0[j],b1[j]);
      }
    }
    __syncthreads();
  }

  float* stg = (float*)smem;
  #pragma unroll
  for (int i=0;i<2;i++){
    int r0 = m0w + i*16 + (lane>>2);
    #pragma unroll
    for (int j=0;j<4;j++){
      int c0 = n0w + j*8 + (lane&3)*2;
      *(float2*)&stg[r0*132 + c0]     = make_float2(d[i][j][0], d[i][j][1]);
      *(float2*)&stg[(r0+8)*132 + c0] = make_float2(d[i][j][2], d[i][j][3]);
    }
  }
  __syncthreads();

  #pragma unroll 1
  for (int q=0;q<8;q++){
    int e = q*256 + tid;
    int rr = e>>5, cc = (e&31)*4;
    float vx = stg[rr*132+cc+0], vy = stg[rr*132+cc+1];
    float vz = stg[rr*132+cc+2], vw = stg[rr*132+cc+3];
    int gcol = col0 + cc, grow = row0 + rr;
    if (epi==1){
      vx = geluf(vx*eg[gcol+0]+eb[gcol+0]);
      vy = geluf(vy*eg[gcol+1]+eb[gcol+1]);
      vz = geluf(vz*eg[gcol+2]+eb[gcol+2]);
      vw = geluf(vw*eg[gcol+3]+eb[gcol+3]);
      *(float4*)(C + (size_t)grow*ldc + gcol) = make_float4(vx,vy,vz,vw);
      __half2* ph = (__half2*)(Cho + (size_t)grow*ldc + gcol);
      ph[0] = __floats2half2_rn(vx,vy);
      ph[1] = __floats2half2_rn(vz,vw);
    } else {
      if (gcol < Nreal)
        *(float4*)(C + (size_t)grow*ldc + gcol) = make_float4(vx,vy,vz,vw);
    }
  }
}

// ---------------- weight prep ----------------
__global__ void prep_inw(const float* __restrict__ in_w){
  int idx = blockIdx.x*256 + threadIdx.x;
  int l = idx / (NPAD_IN*DM); int rem = idx % (NPAD_IN*DM);
  int n = rem / DM, k = rem % DM;
  float v = (n < DINPROJ) ? in_w[((size_t)l*DM + k)*DINPROJ + n] : 0.f;
  g_inwh[idx] = __float2half(v);
}
__global__ void prep_outw(const float* __restrict__ out_w){
  int idx = blockIdx.x*256 + threadIdx.x;
  int l = idx / (DM*DINNER); int rem = idx % (DM*DINNER);
  int n = rem / DINNER, k = rem % DINNER;
  g_owh[idx] = __float2half(out_w[((size_t)l*DINNER + k)*DM + n]);
}
__global__ void prep_w2(const float* __restrict__ w2){
  int idx = blockIdx.x*256 + threadIdx.x;
  g_w2h[idx] = __float2half(w2[idx]);
}

// ---------------- fused stem conv1 -> im2col fp16 ----------------
__global__ __launch_bounds__(128) void conv1_kernel(const float* __restrict__ x,
    const float* __restrict__ w, const float* __restrict__ g1, const float* __restrict__ b1)
{
  __shared__ float swv[C1*27];
  __shared__ float sg[C1], sb[C1];
  __shared__ fp16 sstage[32][516];
  int xx = threadIdx.x, y = blockIdx.x, b = blockIdx.y;
  for (int i=xx;i<C1*27;i+=128) swv[i]=w[i];
  sg[xx]=g1[xx]; sb[xx]=b1[xx];
  __syncthreads();
  float in[27];
  int q=0;
  #pragma unroll
  for (int ci=0;ci<3;ci++)
    #pragma unroll
    for (int ky=0;ky<3;ky++){
      int iy=y+ky-1;
      #pragma unroll
      for (int kx=0;kx<3;kx++){
        int ix=xx+kx-1;
        in[q++] = (iy>=0 && iy<HWD && ix>=0 && ix<HWD) ? x[((b*3+ci)*HWD+iy)*HWD+ix] : 0.f;
      }
    }
  int srow = xx>>2, scol = xx&3;
  for (int co=0;co<C1;co++){
    float acc=0.f;
    #pragma unroll
    for (int t=0;t<27;t++) acc += in[t]*swv[co*27+t];
    sstage[srow][co*4+scol] = __float2half(geluf(acc*sg[co]+sb[co]));
  }
  __syncthreads();
  int ky = y & 3;
  size_t rowbase = (size_t)b*LSEQ + (size_t)(y>>2)*32;
  #pragma unroll 4
  for (int t=0;t<32;t++){
    int id = xx + t*128;
    int r = id >> 7, ci = id & 127;
    *(uint2*)(g_imh + (rowbase + r)*2048 + ci*16 + ky*4) = *(uint2*)&sstage[r][ci*4];
  }
}

// ---------------- fused depthwise conv1d + silu + dt/dA ----------------
#define FUSED_C (CONVDIM+NHEADS)
__global__ void dwdt_kernel(const float* __restrict__ cw, const float* __restrict__ cb,
                            const float* __restrict__ dt_bias, const float* __restrict__ A_log, int layer){
  int idx = blockIdx.x*256 + threadIdx.x;
  if (idx >= NROWS*FUSED_C) return;
  int c = idx % FUSED_C; int row = idx / FUSED_C;
  int l = row & 1023, b = row >> 10;
  if (c < CONVDIM){
    const float* wp = cw + (layer*CONVDIM + c)*4;
    float acc = cb[layer*CONVDIM + c];
    #pragma unroll
    for (int k=0;k<4;k++){
      int ls = l + k - 3;
      if (ls >= 0) acc += g_zx[((size_t)(b<<10)+ls)*DINPROJ + DINNER + c] * wp[k];
    }
    g_xbc[(size_t)row*CONVDIM + c] = siluf(acc);
  } else {
    int h = c - CONVDIM;
    float raw = g_zx[(size_t)row*DINPROJ + 1056 + h] + dt_bias[layer*8+h];
    float dt = (raw > 20.f) ? raw : log1pf(expf(raw));
    float dA = expf(-expf(A_log[layer*8+h])*dt);
    g_dtv[row*8+h] = dt;
    g_dA[(size_t)(b*8+h)*LSEQ + l] = dA;
  }
}

// ---------------- fully fused SSM scan: grid 64 = (b,h), block 1024 = (chunk, p) ----------------
// Phase A: chunk-local scan (states only). Phase B: in-smem chunk prefix combine.
// Phase C: re-scan from correct start state, write y once.
#define SCAN_SMEM (65536*3 + 4096*2 + 64)
__global__ __launch_bounds__(1024,1) void scan_fused_kernel(const float* __restrict__ Dskip, int layer){
  extern __shared__ char smraw[];
  float* sB  = (float*)smraw;                 // [1024][16]
  float* sC  = sB + LSEQ*DSTATE;              // [1024][16]
  float* sS  = sC + LSEQ*DSTATE;              // [16][16*64]  (c, n*64+p)
  float* sdA = sS + NCHUNK*1024;              // [1024]
  float* sdt = sdA + LSEQ;                    // [1024]
  float* sAc = sdt + LSEQ;                    // [16]

  int tid = threadIdx.x;
  int bh = blockIdx.x, b = bh>>3, h = bh&7;
  int c = tid>>6, p = tid&63;

  // cooperative stage of B, C, dA, dt
  const float* xbase = g_xbc + (size_t)b*LSEQ*CONVDIM;
  #pragma unroll
  for (int j=0;j<16;j++){
    int id = tid + j*1024;
    int l = id>>4, n = id&15;
    sB[id] = xbase[(size_t)l*CONVDIM + DINNER + n];
    sC[id] = xbase[(size_t)l*CONVDIM + DINNER + DSTATE + n];
  }
  sdA[tid] = g_dA[(size_t)bh*LSEQ + tid];
  sdt[tid] = g_dtv[((size_t)b*LSEQ + tid)*NHEADS + h];
  __syncthreads();

  // per-chunk decay product
  if (p == 0){
    float r = 1.f;
    #pragma unroll 4
    for (int s=0;s<QCH;s++) r *= sdA[c*QCH+s];
    sAc[c] = r;
  }

  // Phase A: local scan from zero (states only)
  const float* xp = xbase + (size_t)(c*QCH)*CONVDIM + h*HEADDIM + p;
  float hr[DSTATE];
  #pragma unroll
  for (int n=0;n<DSTATE;n++) hr[n]=0.f;
  #pragma unroll 4
  for (int s=0;s<QCH;s++){
    int l = c*QCH+s;
    float xs = xp[(size_t)s*CONVDIM];
    float xv = xs * sdt[l];
    float dAv = sdA[l];
    const float4* Bv = (const float4*)&sB[l*DSTATE];
    float4 b0=Bv[0], b1=Bv[1], b2=Bv[2], b3=Bv[3];
    hr[0]=hr[0]*dAv+xv*b0.x;  hr[1]=hr[1]*dAv+xv*b0.y;
    hr[2]=hr[2]*dAv+xv*b0.z;  hr[3]=hr[3]*dAv+xv*b0.w;
    hr[4]=hr[4]*dAv+xv*b1.x;  hr[5]=hr[5]*dAv+xv*b1.y;
    hr[6]=hr[6]*dAv+xv*b1.z;  hr[7]=hr[7]*dAv+xv*b1.w;
    hr[8]=hr[8]*dAv+xv*b2.x;  hr[9]=hr[9]*dAv+xv*b2.y;
    hr[10]=hr[10]*dAv+xv*b2.z;hr[11]=hr[11]*dAv+xv*b2.w;
    hr[12]=hr[12]*dAv+xv*b3.x;hr[13]=hr[13]*dAv+xv*b3.y;
    hr[14]=hr[14]*dAv+xv*b3.z;hr[15]=hr[15]*dAv+xv*b3.w;
  }
  #pragma unroll
  for (int n=0;n<DSTATE;n++) sS[c*1024 + n*64 + p] = hr[n];
  __syncthreads();

  // Phase B: chunk prefix combine; thread owns slice tid across chunks (in-place)
  {
    float run = 0.f;
    #pragma unroll
    for (int c2=0;c2<NCHUNK;c2++){
      float tmp = sS[c2*1024 + tid];
      sS[c2*1024 + tid] = run;
      run = run*sAc[c2] + tmp;
    }
  }
  __syncthreads();

  // Phase C: re-scan from correct start state, emit y
  #pragma unroll
  for (int n=0;n<DSTATE;n++) hr[n] = sS[c*1024 + n*64 + p];
  float Dh = Dskip[layer*NHEADS+h];
  float* yp = g_ybuf + ((size_t)b*LSEQ + c*QCH)*DINNER + h*HEADDIM + p;
  #pragma unroll 2
  for (int s=0;s<QCH;s++){
    int l = c*QCH+s;
    float xs = xp[(size_t)s*CONVDIM];
    float xv = xs * sdt[l];
    float dAv = sdA[l];
    const float4* Bv = (const float4*)&sB[l*DSTATE];
    const float4* Cv = (const float4*)&sC[l*DSTATE];
    float4 b0=Bv[0], b1=Bv[1], b2=Bv[2], b3=Bv[3];
    float4 c0=Cv[0], c1=Cv[1], c2v=Cv[2], c3=Cv[3];
    float y = xs*Dh;
    hr[0]=hr[0]*dAv+xv*b0.x;   y+=hr[0]*c0.x;
    hr[1]=hr[1]*dAv+xv*b0.y;   y+=hr[1]*c0.y;
    hr[2]=hr[2]*dAv+xv*b0.z;   y+=hr[2]*c0.z;
    hr[3]=hr[3]*dAv+xv*b0.w;   y+=hr[3]*c0.w;
    hr[4]=hr[4]*dAv+xv*b1.x;   y+=hr[4]*c1.x;
    hr[5]=hr[5]*dAv+xv*b1.y;   y+=hr[5]*c1.y;
    hr[6]=hr[6]*dAv+xv*b1.z;   y+=hr[6]*c1.z;
    hr[7]=hr[7]*dAv+xv*b1.w;   y+=hr[7]*c1.w;
    hr[8]=hr[8]*dAv+xv*b2.x;   y+=hr[8]*c2v.x;
    hr[9]=hr[9]*dAv+xv*b2.y;   y+=hr[9]*c2v.y;
    hr[10]=hr[10]*dAv+xv*b2.z; y+=hr[10]*c2v.z;
    hr[11]=hr[11]*dAv+xv*b2.w; y+=hr[11]*c2v.w;
    hr[12]=hr[12]*dAv+xv*b3.x; y+=hr[12]*c3.x;
    hr[13]=hr[13]*dAv+xv*b3.y; y+=hr[13]*c3.y;
    hr[14]=hr[14]*dAv+xv*b3.z; y+=hr[14]*c3.z;
    hr[15]=hr[15]*dAv+xv*b3.w; y+=hr[15]*c3.w;
    yp[(size_t)s*DINNER] = y;
  }
}

// ---------------- gate + RMS-norm -> fp16 ----------------
__global__ __launch_bounds__(128) void gate_kernel(const float* __restrict__ rms_w, int layer){
  __shared__ float sred[32];
  size_t row = blockIdx.x;
  int tid = threadIdx.x;
  float v[4]; float ss = 0.f;
  #pragma unroll
  for (int j=0;j<4;j++){
    int d = tid + j*128;
    float z = g_zx[row*DINPROJ + d];
    float yv = g_ybuf[row*DINNER + d];
    float g = yv * siluf(z);
    v[j]=g; ss += g*g;
  }
  ss = blockReduceSum(ss, sred);
  float rstd = rsqrtf(ss*(1.0f/DINNER) + EPSV);
  #pragma unroll
  for (int j=0;j<4;j++){
    int d = tid + j*128;
    g_gah[row*DINNER + d] = __float2half(v[j]*rstd*rms_w[layer*DINNER + d]);
  }
}

// ---------------- residual + LayerNorm -> tok fp32 + fp16 ----------------
__global__ __launch_bounds__(256) void lnres_kernel(const float* __restrict__ lg, const float* __restrict__ lb, int layer){
  __shared__ float sred[32];
  size_t row = blockIdx.x; int d = threadIdx.x;
  float v = g_mproj[row*DM + d] + g_tok[row*DM + d];
  float mean = blockReduceSum(v, sred) * (1.0f/DM);
  float dv = v - mean;
  float var = blockReduceSum(dv*dv, sred) * (1.0f/DM);
  float o = dv*rsqrtf(var+EPSV)*lg[layer*DM+d] + lb[layer*DM+d];
  g_tok[row*DM + d] = o;
  g_th[row*DM + d] = __float2half(o);
}

// ---------------- grid-wide mean pool over L ----------------
__global__ __launch_bounds__(256) void pool_kernel(){
  __shared__ float s[256];
  int b = blockIdx.x >> 5, cg = blockIdx.x & 31;
  int colq = threadIdx.x & 7, lg = threadIdx.x >> 3;
  int col = cg*8 + colq;
  float acc = 0.f;
  for (int j=0;j<32;j++){
    int l = lg + j*32;
    acc += g_tok[((size_t)b*LSEQ + l)*DM + col];
  }
  s[threadIdx.x] = acc;
  __syncthreads();
  for (int off=16; off>0; off>>=1){
    if (lg < off) s[lg*8+colq] += s[(lg+off)*8+colq];
    __syncthreads();
  }
  if (lg == 0) g_pooled[b*DM + col] = s[colq]*(1.0f/LSEQ);
}

// ---------------- LN + head ----------------
__global__ __launch_bounds__(256) void head_kernel(const float* __restrict__ hg, const float* __restrict__ hb,
    const float* __restrict__ hw, const float* __restrict__ hbias, float* __restrict__ out){
  __shared__ float sred[32];
  __shared__ float sn[DM];
  int b = blockIdx.x, d = threadIdx.x;
  float pooled = g_pooled[b*DM + d];
  float mean = blockReduceSum(pooled, sred)*(1.0f/DM);
  float dv = pooled-mean;
  float var = blockReduceSum(dv*dv, sred)*(1.0f/DM);
  sn[d] = dv*rsqrtf(var+EPSV)*hg[d]+hb[d];
  __syncthreads();
  if (d < 10){
    float acc = hbias[d];
    for (int k=0;k<DM;k++) acc += sn[k]*hw[k*10+d];
    out[b*10+d] = acc;
  }
}

// ---------------- host launcher ----------------
extern "C" void kernel_launch(void* const* d_in, const int* in_sizes, int n_in,
                              void* d_out, int out_size)
{
  const float* x       = (const float*)d_in[0];
  const float* w1      = (const float*)d_in[1];
  const float* sg1     = (const float*)d_in[2];
  const float* sb1     = (const float*)d_in[3];
  const float* w2      = (const float*)d_in[4];
  const float* sg2     = (const float*)d_in[5];
  const float* sb2     = (const float*)d_in[6];
  const float* in_w    = (const float*)d_in[7];
  const float* conv_w  = (const float*)d_in[8];
  const float* conv_b  = (const float*)d_in[9];
  const float* dt_bias = (const float*)d_in[10];
  const float* A_log   = (const float*)d_in[11];
  const float* D_skip  = (const float*)d_in[12];
  const float* rms_w   = (const float*)d_in[13];
  const float* out_w   = (const float*)d_in[14];
  const float* ln_g    = (const float*)d_in[15];
  const float* ln_b    = (const float*)d_in[16];
  const float* hg      = (const float*)d_in[17];
  const float* hb      = (const float*)d_in[18];
  const float* hw      = (const float*)d_in[19];
  const float* hbias   = (const float*)d_in[20];
  float* out = (float*)d_out;

  cudaFuncSetAttribute(mmagemm_kernel, cudaFuncAttributeMaxDynamicSharedMemorySize, MMG_SMEM);
  cudaFuncSetAttribute(scan_fused_kernel, cudaFuncAttributeMaxDynamicSharedMemorySize, SCAN_SMEM);

  void *p;
  cudaGetSymbolAddress(&p, g_imh);  fp16* p_imh = (fp16*)p;
  cudaGetSymbolAddress(&p, g_w2h);  fp16* p_w2h = (fp16*)p;
  cudaGetSymbolAddress(&p, g_tok);  float* p_tok = (float*)p;
  cudaGetSymbolAddress(&p, g_th);   fp16* p_th = (fp16*)p;
  cudaGetSymbolAddress(&p, g_inwh); fp16* p_inwh = (fp16*)p;
  cudaGetSymbolAddress(&p, g_owh);  fp16* p_owh = (fp16*)p;
  cudaGetSymbolAddress(&p, g_zx);   float* p_zx = (float*)p;
  cudaGetSymbolAddress(&p, g_gah);  fp16* p_gah = (fp16*)p;
  cudaGetSymbolAddress(&p, g_mproj);float* p_m = (float*)p;

  conv1_kernel<<<dim3(HWD,BATCH),128>>>(x, w1, sg1, sb1);
  prep_w2<<<(256*2048)/256,256>>>(w2);

  mmagemm_kernel<<<dim3(2,128),256,MMG_SMEM>>>(p_imh, p_w2h,
      p_tok, 2048, 256, 256, 1, sg2, sb2, p_th);

  prep_inw<<<(4*NPAD_IN*DM)/256,256>>>(in_w);
  prep_outw<<<(4*DM*DINNER)/256,256>>>(out_w);

  for (int i=0;i<4;i++){
    mmagemm_kernel<<<dim3(9,128),256,MMG_SMEM>>>(p_th,
        p_inwh + (size_t)i*NPAD_IN*DM,
        p_zx, DM, DINPROJ, DINPROJ, 0, (const float*)0, (const float*)0, (fp16*)0);
    dwdt_kernel<<<(NROWS*FUSED_C+255)/256,256>>>(conv_w, conv_b, dt_bias, A_log, i);
    scan_fused_kernel<<<64,1024,SCAN_SMEM>>>(D_skip, i);
    gate_kernel<<<NROWS,128>>>(rms_w, i);
    mmagemm_kernel<<<dim3(2,128),256,MMG_SMEM>>>(p_gah,
        p_owh + (size_t)i*DM*DINNER,
        p_m, DINNER, DM, DM, 0, (const float*)0, (const float*)0, (fp16*)0);
    lnres_kernel<<<NROWS,256>>>(ln_g, ln_b, i);
  }

  pool_kernel<<<BATCH*32,256>>>();
  head_kernel<<<BATCH,256>>>(hg, hb, hw, hbias, out);
}